// round 2
// baseline (speedup 1.0000x reference)
#include <cuda_runtime.h>
#include <math.h>

// Problem constants
#define BV 4
#define SV 2048
#define DV 1024
constexpr int    BS        = BV * SV;            // 8192 rows per modality
constexpr size_t QKV_ELEMS = (size_t)3 * BS * DV; // 25,165,824
constexpr size_t SC_ELEMS  = (size_t)3 * BV * SV * SV; // 50,331,648

// Static device scratch (no cudaMalloc allowed)
__device__ float g_Q[QKV_ELEMS];
__device__ float g_K[QKV_ELEMS];
__device__ float g_V[QKV_ELEMS];
__device__ float g_Sc[SC_ELEMS];
__device__ float g_Ctx[QKV_ELEMS];

// ---------------------------------------------------------------------------
// Generic 128x128x8 fp32 GEMM block: C_tile = A @ B  (or A @ B^T if TRANS_B).
// 256 threads, 8x8 per-thread microtile. All dims must be multiples of 128/8.
// SPLIT_A: A is a virtual concat [A | A2] along K (split at K/2), both lda.
// Epi(row, col, val) handles the epilogue per element.
// NOTE: plain lambda (no __device__ annotation) — defined inside __global__
// bodies so it is implicitly device code; avoids --extended-lambda.
// ---------------------------------------------------------------------------
template<bool TRANS_B, bool SPLIT_A, class Epi>
__device__ __forceinline__ void sgemm_block(
    const float* __restrict__ A, const float* __restrict__ A2,
    const float* __restrict__ Bmat,
    int K, int lda, int ldb, Epi epi)
{
    const int rowBase = blockIdx.y * 128;
    const int colBase = blockIdx.x * 128;

    __shared__ float As[8][128];
    __shared__ float Bs[8][128];

    const int tid = threadIdx.x;
    const int tx  = tid & 15;       // 0..15 -> N microtile
    const int ty  = tid >> 4;       // 0..15 -> M microtile
    const int lRow = tid >> 1;      // 0..127 (A / NT-B loader row)
    const int lK   = (tid & 1) * 4; // 0 or 4

    float acc[8][8];
#pragma unroll
    for (int i = 0; i < 8; i++)
#pragma unroll
        for (int j = 0; j < 8; j++) acc[i][j] = 0.f;

    const int splitK = SPLIT_A ? (K >> 1) : K;

    for (int k0 = 0; k0 < K; k0 += 8) {
        // ---- load A tile (transposed into As[k][m]) ----
        const float* Ak = A;
        int kk0 = k0;
        if constexpr (SPLIT_A) {
            if (k0 >= splitK) { Ak = A2; kk0 = k0 - splitK; }
        }
        float4 av = *reinterpret_cast<const float4*>(
            Ak + (size_t)(rowBase + lRow) * lda + kk0 + lK);
        As[lK + 0][lRow] = av.x;
        As[lK + 1][lRow] = av.y;
        As[lK + 2][lRow] = av.z;
        As[lK + 3][lRow] = av.w;

        // ---- load B tile ----
        if constexpr (TRANS_B) {
            // B row-major (N x K): same pattern as A, transposed into Bs[k][n]
            float4 bv = *reinterpret_cast<const float4*>(
                Bmat + (size_t)(colBase + lRow) * ldb + k0 + lK);
            Bs[lK + 0][lRow] = bv.x;
            Bs[lK + 1][lRow] = bv.y;
            Bs[lK + 2][lRow] = bv.z;
            Bs[lK + 3][lRow] = bv.w;
        } else {
            // B row-major (K x N): direct copy
            const int bk = tid >> 5;          // 0..7
            const int bn = (tid & 31) << 2;   // 0..124
            *reinterpret_cast<float4*>(&Bs[bk][bn]) =
                *reinterpret_cast<const float4*>(
                    Bmat + (size_t)(k0 + bk) * ldb + colBase + bn);
        }
        __syncthreads();

        // ---- compute ----
#pragma unroll
        for (int kk = 0; kk < 8; kk++) {
            float4 a0 = *reinterpret_cast<const float4*>(&As[kk][ty * 8]);
            float4 a1 = *reinterpret_cast<const float4*>(&As[kk][ty * 8 + 4]);
            float4 b0 = *reinterpret_cast<const float4*>(&Bs[kk][tx * 8]);
            float4 b1 = *reinterpret_cast<const float4*>(&Bs[kk][tx * 8 + 4]);
            float a[8] = {a0.x, a0.y, a0.z, a0.w, a1.x, a1.y, a1.z, a1.w};
            float b[8] = {b0.x, b0.y, b0.z, b0.w, b1.x, b1.y, b1.z, b1.w};
#pragma unroll
            for (int i = 0; i < 8; i++)
#pragma unroll
                for (int j = 0; j < 8; j++)
                    acc[i][j] = fmaf(a[i], b[j], acc[i][j]);
        }
        __syncthreads();
    }

    // ---- epilogue ----
#pragma unroll
    for (int i = 0; i < 8; i++) {
        const int r = rowBase + ty * 8 + i;
#pragma unroll
        for (int j = 0; j < 8; j++) {
            epi(r, colBase + tx * 8 + j, acc[i][j]);
        }
    }
}

// ---------------------------------------------------------------------------
// Kernel 1: Q/K/V projections. grid.z = 9: m = z/3 (modality), t = z%3 (q/k/v)
// Q[m] = X[m] @ Wq[m] + bq[m]   (M=8192, N=1024, K=1024)
// ---------------------------------------------------------------------------
__global__ __launch_bounds__(256)
void qkv_proj_kernel(const float* __restrict__ x1, const float* __restrict__ x2,
                     const float* __restrict__ x3,
                     const float* __restrict__ Wq, const float* __restrict__ bq,
                     const float* __restrict__ Wk, const float* __restrict__ bk,
                     const float* __restrict__ Wv, const float* __restrict__ bv)
{
    const int z = blockIdx.z;
    const int m = z / 3, t = z % 3;
    const float* X = (m == 0) ? x1 : (m == 1) ? x2 : x3;
    const float* W;
    const float* bias;
    float* C;
    if (t == 0)      { W = Wq; bias = bq; C = g_Q; }
    else if (t == 1) { W = Wk; bias = bk; C = g_K; }
    else             { W = Wv; bias = bv; C = g_V; }
    W    += (size_t)m * DV * DV;
    bias += (size_t)m * DV;
    C    += (size_t)m * BS * DV;

    sgemm_block<false, false>(X, nullptr, W, DV, DV, DV,
        [=](int r, int c, float v) {
            C[(size_t)r * DV + c] = v + bias[c];
        });
}

// ---------------------------------------------------------------------------
// Kernel 2: scores[z] = Q[z] @ K[z]^T * (1/sqrt(D)).  z = m*B + b, 12 slices.
// M=N=2048, K=1024
// ---------------------------------------------------------------------------
__global__ __launch_bounds__(256)
void scores_kernel()
{
    const int z = blockIdx.z;
    const float* Qp = g_Q + (size_t)z * SV * DV;
    const float* Kp = g_K + (size_t)z * SV * DV;
    float* Sp = g_Sc + (size_t)z * SV * SV;
    const float scale = 0.03125f; // 1/sqrt(1024)

    sgemm_block<true, false>(Qp, nullptr, Kp, DV, DV, DV,
        [=](int r, int c, float v) {
            Sp[(size_t)r * SV + c] = v * scale;
        });
}

// ---------------------------------------------------------------------------
// Kernel 3: row softmax over the last dim (2048). One block per row.
// ---------------------------------------------------------------------------
__global__ __launch_bounds__(256)
void softmax_kernel()
{
    float* p = g_Sc + (size_t)blockIdx.x * SV;
    const int tid = threadIdx.x;

    float local[8];
    float mx = -INFINITY;
#pragma unroll
    for (int i = 0; i < 8; i++) {
        local[i] = p[tid + i * 256];
        mx = fmaxf(mx, local[i]);
    }

    __shared__ float redMax[8];
    __shared__ float redSum[8];
#pragma unroll
    for (int o = 16; o; o >>= 1)
        mx = fmaxf(mx, __shfl_xor_sync(0xffffffffu, mx, o));
    if ((tid & 31) == 0) redMax[tid >> 5] = mx;
    __syncthreads();
    mx = redMax[0];
#pragma unroll
    for (int w = 1; w < 8; w++) mx = fmaxf(mx, redMax[w]);

    float sum = 0.f;
#pragma unroll
    for (int i = 0; i < 8; i++) {
        local[i] = __expf(local[i] - mx);
        sum += local[i];
    }
#pragma unroll
    for (int o = 16; o; o >>= 1)
        sum += __shfl_xor_sync(0xffffffffu, sum, o);
    if ((tid & 31) == 0) redSum[tid >> 5] = sum;
    __syncthreads();
    sum = redSum[0];
#pragma unroll
    for (int w = 1; w < 8; w++) sum += redSum[w];

    const float inv = 1.0f / sum;
#pragma unroll
    for (int i = 0; i < 8; i++)
        p[tid + i * 256] = local[i] * inv;
}

// ---------------------------------------------------------------------------
// Kernel 4: ctx[z] = attn[z] @ V[(m+1)%3, b].  M=2048, N=1024, K=2048
// ---------------------------------------------------------------------------
__global__ __launch_bounds__(256)
void ctx_kernel()
{
    const int z = blockIdx.z;
    const int m = z / BV, b = z % BV;
    const int mn = (m + 1) % 3;
    const float* Ap = g_Sc + (size_t)z * SV * SV;
    const float* Vp = g_V + ((size_t)mn * BV + b) * SV * DV;
    float* Cp = g_Ctx + (size_t)z * SV * DV;

    sgemm_block<false, false>(Ap, nullptr, Vp, SV, SV, DV,
        [=](int r, int c, float v) {
            Cp[(size_t)r * DV + c] = v;
        });
}

// ---------------------------------------------------------------------------
// Kernel 5: out[m] = X[m] @ Wo_top[m] + Ctx[m] @ Wo_bot[m] + bo[m]
// Implemented as K=2048 GEMM with virtual-concat A = [X | Ctx].
// Writes both out[m] region and the global_feature region.
// ---------------------------------------------------------------------------
__global__ __launch_bounds__(256)
void out_kernel(const float* __restrict__ x1, const float* __restrict__ x2,
                const float* __restrict__ x3,
                const float* __restrict__ Wo, const float* __restrict__ bo,
                float* __restrict__ out)
{
    const int m = blockIdx.z;
    const float* X    = (m == 0) ? x1 : (m == 1) ? x2 : x3;
    const float* A2   = g_Ctx + (size_t)m * BS * DV;
    const float* W    = Wo + (size_t)m * 2 * DV * DV;
    const float* bias = bo + (size_t)m * DV;
    float* o_m = out + (size_t)m * BS * DV;
    float* gf  = out + (size_t)3 * BS * DV;

    sgemm_block<false, true>(X, A2, W, 2 * DV, DV, DV,
        [=](int r, int c, float v) {
            v += bias[c];
            o_m[(size_t)r * DV + c] = v;
            const int b = r >> 11;        // r / S
            const int s = r & (SV - 1);   // r % S
            gf[((size_t)b * 3 * SV + (size_t)m * SV + s) * DV + c] = v;
        });
}

// ---------------------------------------------------------------------------
extern "C" void kernel_launch(void* const* d_in, const int* in_sizes, int n_in,
                              void* d_out, int out_size)
{
    const float* x1 = (const float*)d_in[0];
    const float* x2 = (const float*)d_in[1];
    const float* x3 = (const float*)d_in[2];
    const float* Wq = (const float*)d_in[3];
    const float* bq = (const float*)d_in[4];
    const float* Wk = (const float*)d_in[5];
    const float* bk = (const float*)d_in[6];
    const float* Wv = (const float*)d_in[7];
    const float* bv = (const float*)d_in[8];
    const float* Wo = (const float*)d_in[9];
    const float* bo = (const float*)d_in[10];
    float* out = (float*)d_out;

    // 1) Q/K/V projections: 9 GEMMs (8192 x 1024 x 1024)
    qkv_proj_kernel<<<dim3(DV / 128, BS / 128, 9), 256>>>(
        x1, x2, x3, Wq, bq, Wk, bk, Wv, bv);

    // 2) scores = Q K^T * scale: 12 GEMMs (2048 x 2048 x 1024)
    scores_kernel<<<dim3(SV / 128, SV / 128, 12), 256>>>();

    // 3) row softmax: 12 * 2048 rows
    softmax_kernel<<<3 * BV * SV, 256>>>();

    // 4) ctx = attn @ V_next: 12 GEMMs (2048 x 1024 x 2048)
    ctx_kernel<<<dim3(DV / 128, SV / 128, 12), 256>>>();

    // 5) output projection + global_feature assembly
    out_kernel<<<dim3(DV / 128, BS / 128, 3), 256>>>(x1, x2, x3, Wo, bo, out);
}

// round 9
// speedup vs baseline: 2.1949x; 2.1949x over previous
#include <cuda_runtime.h>
#include <cuda_fp16.h>
#include <mma.h>
#include <cstdint>
#include <math.h>

using namespace nvcuda;

// ---------------------------------------------------------------------------
// Problem constants
// ---------------------------------------------------------------------------
#define BVAL 4
#define SVAL 2048
#define DVAL 1024
constexpr int    BS   = BVAL * SVAL;                     // 8192 rows / modality
constexpr size_t PM   = (size_t)BS * DVAL;               // 8,388,608 / modality
constexpr size_t QKVE = 3 * PM;                          // 25,165,824
constexpr size_t SCE  = (size_t)3 * BVAL * SVAL * SVAL;  // 50,331,648

// ---------------------------------------------------------------------------
// Static device scratch (cudaMalloc forbidden). fp16 hi/lo pairs.
// ---------------------------------------------------------------------------
__device__ __half g_Xhi[QKVE],   g_Xlo[QKVE];
__device__ __half g_Qhi[QKVE],   g_Qlo[QKVE];
__device__ __half g_Khi[QKVE],   g_Klo[QKVE];
__device__ __half g_Vthi[QKVE],  g_Vtlo[QKVE];          // V^T: [m][1024][8192]
__device__ __half g_Ctxhi[QKVE], g_Ctxlo[QKVE];
__device__ __half g_Phi[SCE],    g_Plo[SCE];
__device__ float  g_Sc[SCE];
__device__ __half g_WqThi[3*1024*1024], g_WqTlo[3*1024*1024];
__device__ __half g_WkThi[3*1024*1024], g_WkTlo[3*1024*1024];
__device__ __half g_WvThi[3*1024*1024], g_WvTlo[3*1024*1024];
__device__ __half g_WoThi[3*1024*2048], g_WoTlo[3*1024*2048];

// fp16 hi/lo split
__device__ __forceinline__ void split1(float x, __half& h, __half& l) {
    h = __float2half_rn(x);
    l = __float2half_rn(x - __half2float(h));
}

// ---------------------------------------------------------------------------
// Generic 128x128 GEMM on WMMA (m16n16k16, f32 accum), fp16 hi/lo 3-pass.
// C = sum_seg A[seg](M x segK, row-major lda) @ B[seg](N x segK, row-major ldb)^T
// 256 threads = 8 warps (4x2); warp tile 32x64. K-chunk 16.
// SMEM: 16 KB tiles (Ah, Al, Bh, Bl @ 128x16) + 32 KB staging overlay.
// Loads: plain uint4 with register prefetch double-buffer (no cp.async).
// Epi(row, col, v0, v1) consumes 2 adjacent columns.
// ---------------------------------------------------------------------------
template <class Epi>
__device__ void hgemm(const __half* const* Ah, const __half* const* Al,
                      const __half* const* Bh, const __half* const* Bl,
                      int nseg, int segK, size_t lda, size_t ldb, Epi epi)
{
    __shared__ __align__(16) unsigned char smraw[32768];
    __half* sAh = reinterpret_cast<__half*>(smraw);          // 128x16
    __half* sAl = sAh + 2048;
    __half* sBh = sAh + 4096;
    __half* sBl = sAh + 6144;
    float*  stage = reinterpret_cast<float*>(smraw);         // epilogue overlay

    const int tid  = threadIdx.x;
    const int lane = tid & 31;
    const int wid  = tid >> 5;
    const int wm   = wid >> 1;        // 0..3 (M groups of 32)
    const int wn   = wid & 1;         // 0..1 (N groups of 64)
    const int rowBase = blockIdx.y * 128;
    const int colBase = blockIdx.x * 128;

    wmma::fragment<wmma::accumulator, 16, 16, 16, float> acc[2][4];
#pragma unroll
    for (int mt = 0; mt < 2; mt++)
#pragma unroll
        for (int nt = 0; nt < 4; nt++) wmma::fill_fragment(acc[mt][nt], 0.0f);

    const int chunksPerSeg = segK >> 4;
    const int nChunks = nseg * chunksPerSeg;

    // loader: thread covers (row lr, 16B-subchunk lc) of each 128x16 tile
    const int lr = tid >> 1;
    const int lc = tid & 1;
    const int soff = lr * 16 + lc * 8;   // halves

    uint4 pAh, pAl, pBh, pBl;
    auto prefetch = [&](int cIdx) {
        const int seg = cIdx / chunksPerSeg;
        const int kk  = (cIdx - seg * chunksPerSeg) << 4;
        const size_t ao = (size_t)(rowBase + lr) * lda + kk + lc * 8;
        const size_t bo = (size_t)(colBase + lr) * ldb + kk + lc * 8;
        pAh = *reinterpret_cast<const uint4*>(Ah[seg] + ao);
        pAl = *reinterpret_cast<const uint4*>(Al[seg] + ao);
        pBh = *reinterpret_cast<const uint4*>(Bh[seg] + bo);
        pBl = *reinterpret_cast<const uint4*>(Bl[seg] + bo);
    };

    prefetch(0);

    for (int c = 0; c < nChunks; c++) {
        __syncthreads();   // previous chunk's compute done -> tiles reusable
        *reinterpret_cast<uint4*>(sAh + soff) = pAh;
        *reinterpret_cast<uint4*>(sAl + soff) = pAl;
        *reinterpret_cast<uint4*>(sBh + soff) = pBh;
        *reinterpret_cast<uint4*>(sBl + soff) = pBl;
        __syncthreads();
        if (c + 1 < nChunks) prefetch(c + 1);   // overlap with compute below

        wmma::fragment<wmma::matrix_a, 16, 16, 16, __half, wmma::row_major> fah[2], fal[2];
#pragma unroll
        for (int mt = 0; mt < 2; mt++) {
            const int r = wm * 32 + mt * 16;
            wmma::load_matrix_sync(fah[mt], sAh + r * 16, 16);
            wmma::load_matrix_sync(fal[mt], sAl + r * 16, 16);
        }
#pragma unroll
        for (int nt = 0; nt < 4; nt++) {
            wmma::fragment<wmma::matrix_b, 16, 16, 16, __half, wmma::col_major> fbh, fbl;
            const int n = wn * 64 + nt * 16;
            wmma::load_matrix_sync(fbh, sBh + n * 16, 16);
            wmma::load_matrix_sync(fbl, sBl + n * 16, 16);
#pragma unroll
            for (int mt = 0; mt < 2; mt++) {
                wmma::mma_sync(acc[mt][nt], fah[mt], fbh, acc[mt][nt]);
                wmma::mma_sync(acc[mt][nt], fal[mt], fbh, acc[mt][nt]);
                wmma::mma_sync(acc[mt][nt], fah[mt], fbl, acc[mt][nt]);
            }
        }
    }

    // epilogue via staging overlay: warp-private 16x64 f32 region
    __syncthreads();   // all compute done before tiles are overwritten
    float* st = stage + wid * 1024;
#pragma unroll
    for (int mt = 0; mt < 2; mt++) {
#pragma unroll
        for (int nt = 0; nt < 4; nt++)
            wmma::store_matrix_sync(st + nt * 16, acc[mt][nt], 64, wmma::mem_row_major);
        __syncwarp();
#pragma unroll
        for (int j = 0; j < 16; j++) {
            float2 v = *reinterpret_cast<float2*>(st + j * 64 + 2 * lane);
            epi(rowBase + wm * 32 + mt * 16 + j, colBase + wn * 64 + 2 * lane, v.x, v.y);
        }
        __syncwarp();
    }
}

// ---------------------------------------------------------------------------
// Conversion: X (fp32) -> Xhi/Xlo  [m][8192][1024]
// ---------------------------------------------------------------------------
__global__ __launch_bounds__(256)
void conv_x(const float* __restrict__ x1, const float* __restrict__ x2,
            const float* __restrict__ x3)
{
    size_t t = (size_t)blockIdx.x * blockDim.x + threadIdx.x;   // float4 index
    const size_t PM4 = PM / 4;
    int m = (int)(t / PM4);
    size_t i = t - (size_t)m * PM4;
    const float* X = (m == 0) ? x1 : (m == 1) ? x2 : x3;
    float4 v = reinterpret_cast<const float4*>(X)[i];
    __half h[4], l[4];
    split1(v.x, h[0], l[0]); split1(v.y, h[1], l[1]);
    split1(v.z, h[2], l[2]); split1(v.w, h[3], l[3]);
    size_t o = (size_t)m * PM + i * 4;
    __half2* ph = reinterpret_cast<__half2*>(g_Xhi + o);
    __half2* pl = reinterpret_cast<__half2*>(g_Xlo + o);
    ph[0] = __halves2half2(h[0], h[1]); ph[1] = __halves2half2(h[2], h[3]);
    pl[0] = __halves2half2(l[0], l[1]); pl[1] = __halves2half2(l[2], l[3]);
}

// ---------------------------------------------------------------------------
// Transpose + split weights: W[m][rows][cols] -> WT[m][cols][rows] hi/lo.
// Destination globals are resolved IN DEVICE CODE via `sel` (0=Wq,1=Wk,2=Wv,3=Wo)
// — passing __device__ symbols as host-side kernel args gives the host shadow
// address (that was the R4-R7 bug: weights stayed zero on device).
// ---------------------------------------------------------------------------
__global__ void convT_sel(const float* __restrict__ W, int sel, int rows, int cols)
{
    __half* hi;
    __half* lo;
    switch (sel) {
        case 0:  hi = g_WqThi; lo = g_WqTlo; break;
        case 1:  hi = g_WkThi; lo = g_WkTlo; break;
        case 2:  hi = g_WvThi; lo = g_WvTlo; break;
        default: hi = g_WoThi; lo = g_WoTlo; break;
    }
    __shared__ float tile[32][33];
    const float* Wm = W + (size_t)blockIdx.z * rows * cols;
    const int c0 = blockIdx.x * 32, r0 = blockIdx.y * 32;
    const int tx = threadIdx.x;
    for (int dy = threadIdx.y; dy < 32; dy += 8)
        tile[dy][tx] = Wm[(size_t)(r0 + dy) * cols + c0 + tx];
    __syncthreads();
    const size_t ob = (size_t)blockIdx.z * rows * cols;
    for (int dy = threadIdx.y; dy < 32; dy += 8) {
        float v = tile[tx][dy];
        __half h, l;
        split1(v, h, l);
        size_t o = ob + (size_t)(c0 + dy) * rows + r0 + tx;
        hi[o] = h; lo[o] = l;
    }
}

// ---------------------------------------------------------------------------
// Q/K projections. z = m*2 + t (t: 0=Q, 1=K).  M=8192, N=1024, K=1024
// ---------------------------------------------------------------------------
__global__ __launch_bounds__(256)
void qk_proj(const float* __restrict__ bq, const float* __restrict__ bk)
{
    const int z = blockIdx.z;
    const int m = z >> 1, t = z & 1;
    const __half* Ah[1] = {g_Xhi + (size_t)m * PM};
    const __half* Al[1] = {g_Xlo + (size_t)m * PM};
    const __half* Bh[1] = {(t ? g_WkThi : g_WqThi) + (size_t)m * 1024 * 1024};
    const __half* Bl[1] = {(t ? g_WkTlo : g_WqTlo) + (size_t)m * 1024 * 1024};
    const float* bias = (t ? bk : bq) + m * 1024;
    __half* Ch = (t ? g_Khi : g_Qhi) + (size_t)m * PM;
    __half* Cl = (t ? g_Klo : g_Qlo) + (size_t)m * PM;

    hgemm(Ah, Al, Bh, Bl, 1, 1024, 1024, 1024,
        [=](int r, int c, float v0, float v1) {
            __half h0, l0, h1, l1;
            split1(v0 + bias[c],     h0, l0);
            split1(v1 + bias[c + 1], h1, l1);
            size_t o = (size_t)r * 1024 + c;
            *reinterpret_cast<__half2*>(Ch + o) = __halves2half2(h0, h1);
            *reinterpret_cast<__half2*>(Cl + o) = __halves2half2(l0, l1);
        });
}

// ---------------------------------------------------------------------------
// V^T projection: Vt[m] = WvT[m] @ X[m]^T + bv.  M=1024(d), N=8192(tok), K=1024
// ---------------------------------------------------------------------------
__global__ __launch_bounds__(256)
void vt_proj(const float* __restrict__ bv)
{
    const int m = blockIdx.z;
    const __half* Ah[1] = {g_WvThi + (size_t)m * 1024 * 1024};
    const __half* Al[1] = {g_WvTlo + (size_t)m * 1024 * 1024};
    const __half* Bh[1] = {g_Xhi + (size_t)m * PM};
    const __half* Bl[1] = {g_Xlo + (size_t)m * PM};
    const float* bias = bv + m * 1024;
    __half* Ch = g_Vthi + (size_t)m * PM;
    __half* Cl = g_Vtlo + (size_t)m * PM;

    hgemm(Ah, Al, Bh, Bl, 1, 1024, 1024, 1024,
        [=](int r, int c, float v0, float v1) {
            const float bb = bias[r];
            __half h0, l0, h1, l1;
            split1(v0 + bb, h0, l0);
            split1(v1 + bb, h1, l1);
            size_t o = (size_t)r * 8192 + c;
            *reinterpret_cast<__half2*>(Ch + o) = __halves2half2(h0, h1);
            *reinterpret_cast<__half2*>(Cl + o) = __halves2half2(l0, l1);
        });
}

// ---------------------------------------------------------------------------
// scores[z] = Q[z] @ K[z]^T * scale (fp32).  z = m*4+b.  M=N=2048, K=1024
// ---------------------------------------------------------------------------
__global__ __launch_bounds__(256)
void scores_kernel()
{
    const int z = blockIdx.z;
    const size_t off = ((size_t)(z >> 2) * BS + (size_t)(z & 3) * SVAL) * DVAL;
    const __half* Ah[1] = {g_Qhi + off};
    const __half* Al[1] = {g_Qlo + off};
    const __half* Bh[1] = {g_Khi + off};
    const __half* Bl[1] = {g_Klo + off};
    float* Sp = g_Sc + (size_t)z * SVAL * SVAL;

    hgemm(Ah, Al, Bh, Bl, 1, 1024, 1024, 1024,
        [=](int r, int c, float v0, float v1) {
            float2 f; f.x = v0 * 0.03125f; f.y = v1 * 0.03125f;
            *reinterpret_cast<float2*>(Sp + (size_t)r * SVAL + c) = f;
        });
}

// ---------------------------------------------------------------------------
// softmax rows of 2048: g_Sc (fp32) -> g_Phi/g_Plo (fp16 hi/lo)
// ---------------------------------------------------------------------------
__global__ __launch_bounds__(256)
void softmax_kernel()
{
    const size_t row = blockIdx.x;
    const float* p = g_Sc + row * SVAL;
    const int tid = threadIdx.x;

    float4 v0 = reinterpret_cast<const float4*>(p)[tid * 2];
    float4 v1 = reinterpret_cast<const float4*>(p)[tid * 2 + 1];
    float vals[8] = {v0.x, v0.y, v0.z, v0.w, v1.x, v1.y, v1.z, v1.w};

    float mx = vals[0];
#pragma unroll
    for (int i = 1; i < 8; i++) mx = fmaxf(mx, vals[i]);
    __shared__ float red[8];
#pragma unroll
    for (int o = 16; o; o >>= 1) mx = fmaxf(mx, __shfl_xor_sync(0xffffffffu, mx, o));
    if ((tid & 31) == 0) red[tid >> 5] = mx;
    __syncthreads();
    mx = red[0];
#pragma unroll
    for (int w = 1; w < 8; w++) mx = fmaxf(mx, red[w]);
    __syncthreads();

    float sum = 0.f;
#pragma unroll
    for (int i = 0; i < 8; i++) { vals[i] = __expf(vals[i] - mx); sum += vals[i]; }
#pragma unroll
    for (int o = 16; o; o >>= 1) sum += __shfl_xor_sync(0xffffffffu, sum, o);
    if ((tid & 31) == 0) red[tid >> 5] = sum;
    __syncthreads();
    sum = red[0];
#pragma unroll
    for (int w = 1; w < 8; w++) sum += red[w];
    const float inv = 1.0f / sum;

    alignas(16) __half h[8], l[8];
#pragma unroll
    for (int i = 0; i < 8; i++) split1(vals[i] * inv, h[i], l[i]);
    reinterpret_cast<uint4*>(g_Phi + row * SVAL)[tid] = *reinterpret_cast<uint4*>(h);
    reinterpret_cast<uint4*>(g_Plo + row * SVAL)[tid] = *reinterpret_cast<uint4*>(l);
}

// ---------------------------------------------------------------------------
// ctx[z] = P[z] @ Vt[(m+1)%3, b]^T.  M=2048(s), N=1024(d), K=2048
// ---------------------------------------------------------------------------
__global__ __launch_bounds__(256)
void ctx_kernel()
{
    const int z = blockIdx.z;
    const int m = z >> 2, b = z & 3;
    const int mn = (m + 1) % 3;
    const size_t aoff = (size_t)z * SVAL * SVAL;
    const size_t boff = (size_t)mn * PM + (size_t)b * SVAL;
    const __half* Ah[1] = {g_Phi + aoff};
    const __half* Al[1] = {g_Plo + aoff};
    const __half* Bh[1] = {g_Vthi + boff};
    const __half* Bl[1] = {g_Vtlo + boff};
    __half* Ch = g_Ctxhi + ((size_t)m * BS + (size_t)b * SVAL) * DVAL;
    __half* Cl = g_Ctxlo + ((size_t)m * BS + (size_t)b * SVAL) * DVAL;

    hgemm(Ah, Al, Bh, Bl, 1, 2048, 2048, 8192,
        [=](int r, int c, float v0, float v1) {
            __half h0, l0, h1, l1;
            split1(v0, h0, l0);
            split1(v1, h1, l1);
            size_t o = (size_t)r * DVAL + c;
            *reinterpret_cast<__half2*>(Ch + o) = __halves2half2(h0, h1);
            *reinterpret_cast<__half2*>(Cl + o) = __halves2half2(l0, l1);
        });
}

// ---------------------------------------------------------------------------
// out[m] = [X|Ctx][m] @ WoT[m]^T + bo.  M=8192, N=1024, K=2x1024 (2 segments)
// ---------------------------------------------------------------------------
__global__ __launch_bounds__(256)
void out_kernel(const float* __restrict__ bo, float* __restrict__ out)
{
    const int m = blockIdx.z;
    const size_t xo = (size_t)m * PM;
    const __half* Wh = g_WoThi + (size_t)m * 1024 * 2048;
    const __half* Wl = g_WoTlo + (size_t)m * 1024 * 2048;
    const __half* Ah[2] = {g_Xhi + xo, g_Ctxhi + xo};
    const __half* Al[2] = {g_Xlo + xo, g_Ctxlo + xo};
    const __half* Bh[2] = {Wh, Wh + 1024};
    const __half* Bl[2] = {Wl, Wl + 1024};
    const float* bias = bo + m * 1024;
    float* o_m = out + (size_t)m * PM;
    float* gf  = out + (size_t)3 * PM;

    hgemm(Ah, Al, Bh, Bl, 2, 1024, 1024, 2048,
        [=](int r, int c, float v0, float v1) {
            float2 f;
            f.x = v0 + bias[c];
            f.y = v1 + bias[c + 1];
            const size_t o1 = (size_t)r * DVAL + c;
            const int bb = r >> 11, ss = r & (SVAL - 1);
            const size_t o2 = ((size_t)bb * 3 * SVAL + (size_t)m * SVAL + ss) * DVAL + c;
            *reinterpret_cast<float2*>(o_m + o1) = f;
            *reinterpret_cast<float2*>(gf  + o2) = f;
        });
}

// ---------------------------------------------------------------------------
extern "C" void kernel_launch(void* const* d_in, const int* in_sizes, int n_in,
                              void* d_out, int out_size)
{
    const float* x1 = (const float*)d_in[0];
    const float* x2 = (const float*)d_in[1];
    const float* x3 = (const float*)d_in[2];
    const float* Wq = (const float*)d_in[3];
    const float* bq = (const float*)d_in[4];
    const float* Wk = (const float*)d_in[5];
    const float* bk = (const float*)d_in[6];
    const float* Wv = (const float*)d_in[7];
    const float* bv = (const float*)d_in[8];
    const float* Wo = (const float*)d_in[9];
    const float* bo = (const float*)d_in[10];
    float* out = (float*)d_out;

    // input conversions (destinations resolved in device code)
    conv_x<<<(unsigned)(3 * PM / 4 / 256), 256>>>(x1, x2, x3);
    {
        dim3 blk(32, 8);
        convT_sel<<<dim3(32, 32, 3), blk>>>(Wq, 0, 1024, 1024);
        convT_sel<<<dim3(32, 32, 3), blk>>>(Wk, 1, 1024, 1024);
        convT_sel<<<dim3(32, 32, 3), blk>>>(Wv, 2, 1024, 1024);
        convT_sel<<<dim3(32, 64, 3), blk>>>(Wo, 3, 2048, 1024);
    }

    qk_proj       <<<dim3(8, 64, 6),   256>>>(bq, bk);
    vt_proj       <<<dim3(64, 8, 3),   256>>>(bv);
    scores_kernel <<<dim3(16, 16, 12), 256>>>();
    softmax_kernel<<<3 * BVAL * SVAL,  256>>>();
    ctx_kernel    <<<dim3(8, 16, 12),  256>>>();
    out_kernel    <<<dim3(8, 64, 3),   256>>>(bo, out);
}

// round 10
// speedup vs baseline: 2.6933x; 1.2270x over previous
#include <cuda_runtime.h>
#include <cuda_fp16.h>
#include <mma.h>
#include <cstdint>
#include <math.h>

using namespace nvcuda;

// ---------------------------------------------------------------------------
// Problem constants
// ---------------------------------------------------------------------------
#define BVAL 4
#define SVAL 2048
#define DVAL 1024
constexpr int    BS   = BVAL * SVAL;                     // 8192 rows / modality
constexpr size_t PM   = (size_t)BS * DVAL;               // 8,388,608 / modality
constexpr size_t QKVE = 3 * PM;                          // 25,165,824
constexpr size_t SCE  = (size_t)3 * BVAL * SVAL * SVAL;  // 50,331,648

// ---------------------------------------------------------------------------
// Static device scratch (cudaMalloc forbidden). fp16 hi/lo pairs.
// ---------------------------------------------------------------------------
__device__ __half g_Xhi[QKVE],   g_Xlo[QKVE];
__device__ __half g_Qhi[QKVE],   g_Qlo[QKVE];
__device__ __half g_Khi[QKVE],   g_Klo[QKVE];
__device__ __half g_Vthi[QKVE],  g_Vtlo[QKVE];          // V^T: [m][1024][8192]
__device__ __half g_Ctxhi[QKVE], g_Ctxlo[QKVE];
__device__ __half g_Phi[SCE],    g_Plo[SCE];
__device__ float  g_Sc[SCE];
__device__ __half g_WqThi[3*1024*1024], g_WqTlo[3*1024*1024];
__device__ __half g_WkThi[3*1024*1024], g_WkTlo[3*1024*1024];
__device__ __half g_WvThi[3*1024*1024], g_WvTlo[3*1024*1024];
__device__ __half g_WoThi[3*1024*2048], g_WoTlo[3*1024*2048];

// fp16 hi/lo split
__device__ __forceinline__ void split1(float x, __half& h, __half& l) {
    h = __float2half_rn(x);
    l = __float2half_rn(x - __half2float(h));
}

__device__ __forceinline__ uint32_t smem_u32(const void* p) {
    uint32_t a;
    asm("{ .reg .u64 t; cvta.to.shared.u64 t, %1; cvt.u32.u64 %0, t; }"
        : "=r"(a) : "l"(p));
    return a;
}

__device__ __forceinline__ void cpa16(uint32_t dst, const void* src) {
    asm volatile("cp.async.cg.shared.global [%0], [%1], 16;"
                 :: "r"(dst), "l"(src) : "memory");
}

// ---------------------------------------------------------------------------
// Generic 128x128 GEMM on WMMA (m16n16k16, f32 accum), fp16 hi/lo 3-pass.
// C = sum_seg A[seg](M x segK, row-major lda) @ B[seg](N x segK, row-major ldb)^T
// 256 threads = 8 warps (4x2); warp tile 32x64. K-chunk 16.
// 3-stage cp.async pipeline; 48 KB static SMEM (3 x 16 KB stages),
// epilogue staging overlays the same SMEM. One __syncthreads per chunk.
// Epi(row, col, v0, v1) consumes 2 adjacent columns.
// ---------------------------------------------------------------------------
template <class Epi>
__device__ void hgemm(const __half* const* Ah, const __half* const* Al,
                      const __half* const* Bh, const __half* const* Bl,
                      int nseg, int segK, size_t lda, size_t ldb, Epi epi)
{
    __shared__ __align__(16) unsigned char smraw[49152];   // 3 stages x 16 KB
    float* stage = reinterpret_cast<float*>(smraw);        // epilogue overlay
    const uint32_t sb = smem_u32(smraw);

    const int tid  = threadIdx.x;
    const int lane = tid & 31;
    const int wid  = tid >> 5;
    const int wm   = wid >> 1;        // 0..3 (M groups of 32)
    const int wn   = wid & 1;         // 0..1 (N groups of 64)
    const int rowBase = blockIdx.y * 128;
    const int colBase = blockIdx.x * 128;

    wmma::fragment<wmma::accumulator, 16, 16, 16, float> acc[2][4];
#pragma unroll
    for (int mt = 0; mt < 2; mt++)
#pragma unroll
        for (int nt = 0; nt < 4; nt++) wmma::fill_fragment(acc[mt][nt], 0.0f);

    const int chunksPerSeg = segK >> 4;
    const int nChunks = nseg * chunksPerSeg;

    // loader: thread covers (row lr, 16B-subchunk lc) of each 128x16 tile
    const int lr = tid >> 1;
    const int lc = tid & 1;
    const uint32_t sOffB = (uint32_t)(lr * 16 + lc * 8) * 2u;  // byte offset in tile

    auto issue = [&](int cIdx) {
        const int s   = cIdx % 3;
        const int seg = cIdx / chunksPerSeg;
        const int kk  = (cIdx - seg * chunksPerSeg) << 4;
        const size_t ao = (size_t)(rowBase + lr) * lda + kk + lc * 8;
        const size_t bo = (size_t)(colBase + lr) * ldb + kk + lc * 8;
        const uint32_t base = sb + (uint32_t)s * 16384u + sOffB;
        cpa16(base +     0u, Ah[seg] + ao);
        cpa16(base +  4096u, Al[seg] + ao);
        cpa16(base +  8192u, Bh[seg] + bo);
        cpa16(base + 12288u, Bl[seg] + bo);
        asm volatile("cp.async.commit_group;" ::: "memory");
    };

    issue(0);
    if (nChunks > 1) issue(1);

    for (int c = 0; c < nChunks; c++) {
        if (c + 1 < nChunks)
            asm volatile("cp.async.wait_group 1;" ::: "memory");
        else
            asm volatile("cp.async.wait_group 0;" ::: "memory");
        __syncthreads();   // stage c visible to all; prev compute (c-1) done by all

        __half* sAh = reinterpret_cast<__half*>(smraw + (c % 3) * 16384);
        __half* sAl = sAh + 2048;
        __half* sBh = sAh + 4096;
        __half* sBl = sAh + 6144;

        wmma::fragment<wmma::matrix_a, 16, 16, 16, __half, wmma::row_major> fah[2], fal[2];
#pragma unroll
        for (int mt = 0; mt < 2; mt++) {
            const int r = wm * 32 + mt * 16;
            wmma::load_matrix_sync(fah[mt], sAh + r * 16, 16);
            wmma::load_matrix_sync(fal[mt], sAl + r * 16, 16);
        }
#pragma unroll
        for (int nt = 0; nt < 4; nt++) {
            wmma::fragment<wmma::matrix_b, 16, 16, 16, __half, wmma::col_major> fbh, fbl;
            const int n = wn * 64 + nt * 16;
            wmma::load_matrix_sync(fbh, sBh + n * 16, 16);
            wmma::load_matrix_sync(fbl, sBl + n * 16, 16);
#pragma unroll
            for (int mt = 0; mt < 2; mt++) {
                wmma::mma_sync(acc[mt][nt], fah[mt], fbh, acc[mt][nt]);
                wmma::mma_sync(acc[mt][nt], fal[mt], fbh, acc[mt][nt]);
                wmma::mma_sync(acc[mt][nt], fah[mt], fbl, acc[mt][nt]);
            }
        }

        // stage (c+2)%3 == (c-1)%3: its last readers (compute c-1) all passed
        // the __syncthreads above, so it is safe to overwrite now.
        if (c + 2 < nChunks) issue(c + 2);
    }

    // epilogue via staging overlay: warp-private 16x64 f32 region
    __syncthreads();   // all compute done before tiles are overwritten
    float* st = stage + wid * 1024;
#pragma unroll
    for (int mt = 0; mt < 2; mt++) {
#pragma unroll
        for (int nt = 0; nt < 4; nt++)
            wmma::store_matrix_sync(st + nt * 16, acc[mt][nt], 64, wmma::mem_row_major);
        __syncwarp();
#pragma unroll
        for (int j = 0; j < 16; j++) {
            float2 v = *reinterpret_cast<float2*>(st + j * 64 + 2 * lane);
            epi(rowBase + wm * 32 + mt * 16 + j, colBase + wn * 64 + 2 * lane, v.x, v.y);
        }
        __syncwarp();
    }
}

// ---------------------------------------------------------------------------
// Conversion: X (fp32) -> Xhi/Xlo  [m][8192][1024]
// ---------------------------------------------------------------------------
__global__ __launch_bounds__(256)
void conv_x(const float* __restrict__ x1, const float* __restrict__ x2,
            const float* __restrict__ x3)
{
    size_t t = (size_t)blockIdx.x * blockDim.x + threadIdx.x;   // float4 index
    const size_t PM4 = PM / 4;
    int m = (int)(t / PM4);
    size_t i = t - (size_t)m * PM4;
    const float* X = (m == 0) ? x1 : (m == 1) ? x2 : x3;
    float4 v = reinterpret_cast<const float4*>(X)[i];
    __half h[4], l[4];
    split1(v.x, h[0], l[0]); split1(v.y, h[1], l[1]);
    split1(v.z, h[2], l[2]); split1(v.w, h[3], l[3]);
    size_t o = (size_t)m * PM + i * 4;
    __half2* ph = reinterpret_cast<__half2*>(g_Xhi + o);
    __half2* pl = reinterpret_cast<__half2*>(g_Xlo + o);
    ph[0] = __halves2half2(h[0], h[1]); ph[1] = __halves2half2(h[2], h[3]);
    pl[0] = __halves2half2(l[0], l[1]); pl[1] = __halves2half2(l[2], l[3]);
}

// ---------------------------------------------------------------------------
// Transpose + split weights: W[m][rows][cols] -> WT[m][cols][rows] hi/lo.
// Destination globals resolved IN DEVICE CODE via `sel` (0=Wq,1=Wk,2=Wv,3=Wo)
// — host-passed __device__ symbols resolve to the host shadow (R4-R7 bug).
// ---------------------------------------------------------------------------
__global__ void convT_sel(const float* __restrict__ W, int sel, int rows, int cols)
{
    __half* hi;
    __half* lo;
    switch (sel) {
        case 0:  hi = g_WqThi; lo = g_WqTlo; break;
        case 1:  hi = g_WkThi; lo = g_WkTlo; break;
        case 2:  hi = g_WvThi; lo = g_WvTlo; break;
        default: hi = g_WoThi; lo = g_WoTlo; break;
    }
    __shared__ float tile[32][33];
    const float* Wm = W + (size_t)blockIdx.z * rows * cols;
    const int c0 = blockIdx.x * 32, r0 = blockIdx.y * 32;
    const int tx = threadIdx.x;
    for (int dy = threadIdx.y; dy < 32; dy += 8)
        tile[dy][tx] = Wm[(size_t)(r0 + dy) * cols + c0 + tx];
    __syncthreads();
    const size_t ob = (size_t)blockIdx.z * rows * cols;
    for (int dy = threadIdx.y; dy < 32; dy += 8) {
        float v = tile[tx][dy];
        __half h, l;
        split1(v, h, l);
        size_t o = ob + (size_t)(c0 + dy) * rows + r0 + tx;
        hi[o] = h; lo[o] = l;
    }
}

// ---------------------------------------------------------------------------
// Q/K projections. z = m*2 + t (t: 0=Q, 1=K).  M=8192, N=1024, K=1024
// ---------------------------------------------------------------------------
__global__ __launch_bounds__(256)
void qk_proj(const float* __restrict__ bq, const float* __restrict__ bk)
{
    const int z = blockIdx.z;
    const int m = z >> 1, t = z & 1;
    const __half* Ah[1] = {g_Xhi + (size_t)m * PM};
    const __half* Al[1] = {g_Xlo + (size_t)m * PM};
    const __half* Bh[1] = {(t ? g_WkThi : g_WqThi) + (size_t)m * 1024 * 1024};
    const __half* Bl[1] = {(t ? g_WkTlo : g_WqTlo) + (size_t)m * 1024 * 1024};
    const float* bias = (t ? bk : bq) + m * 1024;
    __half* Ch = (t ? g_Khi : g_Qhi) + (size_t)m * PM;
    __half* Cl = (t ? g_Klo : g_Qlo) + (size_t)m * PM;

    hgemm(Ah, Al, Bh, Bl, 1, 1024, 1024, 1024,
        [=](int r, int c, float v0, float v1) {
            __half h0, l0, h1, l1;
            split1(v0 + bias[c],     h0, l0);
            split1(v1 + bias[c + 1], h1, l1);
            size_t o = (size_t)r * 1024 + c;
            *reinterpret_cast<__half2*>(Ch + o) = __halves2half2(h0, h1);
            *reinterpret_cast<__half2*>(Cl + o) = __halves2half2(l0, l1);
        });
}

// ---------------------------------------------------------------------------
// V^T projection: Vt[m] = WvT[m] @ X[m]^T + bv.  M=1024(d), N=8192(tok), K=1024
// ---------------------------------------------------------------------------
__global__ __launch_bounds__(256)
void vt_proj(const float* __restrict__ bv)
{
    const int m = blockIdx.z;
    const __half* Ah[1] = {g_WvThi + (size_t)m * 1024 * 1024};
    const __half* Al[1] = {g_WvTlo + (size_t)m * 1024 * 1024};
    const __half* Bh[1] = {g_Xhi + (size_t)m * PM};
    const __half* Bl[1] = {g_Xlo + (size_t)m * PM};
    const float* bias = bv + m * 1024;
    __half* Ch = g_Vthi + (size_t)m * PM;
    __half* Cl = g_Vtlo + (size_t)m * PM;

    hgemm(Ah, Al, Bh, Bl, 1, 1024, 1024, 1024,
        [=](int r, int c, float v0, float v1) {
            const float bb = bias[r];
            __half h0, l0, h1, l1;
            split1(v0 + bb, h0, l0);
            split1(v1 + bb, h1, l1);
            size_t o = (size_t)r * 8192 + c;
            *reinterpret_cast<__half2*>(Ch + o) = __halves2half2(h0, h1);
            *reinterpret_cast<__half2*>(Cl + o) = __halves2half2(l0, l1);
        });
}

// ---------------------------------------------------------------------------
// scores[z] = Q[z] @ K[z]^T * scale (fp32).  z = m*4+b.  M=N=2048, K=1024
// ---------------------------------------------------------------------------
__global__ __launch_bounds__(256)
void scores_kernel()
{
    const int z = blockIdx.z;
    const size_t off = ((size_t)(z >> 2) * BS + (size_t)(z & 3) * SVAL) * DVAL;
    const __half* Ah[1] = {g_Qhi + off};
    const __half* Al[1] = {g_Qlo + off};
    const __half* Bh[1] = {g_Khi + off};
    const __half* Bl[1] = {g_Klo + off};
    float* Sp = g_Sc + (size_t)z * SVAL * SVAL;

    hgemm(Ah, Al, Bh, Bl, 1, 1024, 1024, 1024,
        [=](int r, int c, float v0, float v1) {
            float2 f; f.x = v0 * 0.03125f; f.y = v1 * 0.03125f;
            *reinterpret_cast<float2*>(Sp + (size_t)r * SVAL + c) = f;
        });
}

// ---------------------------------------------------------------------------
// softmax rows of 2048: g_Sc (fp32) -> g_Phi/g_Plo (fp16 hi/lo)
// ---------------------------------------------------------------------------
__global__ __launch_bounds__(256)
void softmax_kernel()
{
    const size_t row = blockIdx.x;
    const float* p = g_Sc + row * SVAL;
    const int tid = threadIdx.x;

    float4 v0 = reinterpret_cast<const float4*>(p)[tid * 2];
    float4 v1 = reinterpret_cast<const float4*>(p)[tid * 2 + 1];
    float vals[8] = {v0.x, v0.y, v0.z, v0.w, v1.x, v1.y, v1.z, v1.w};

    float mx = vals[0];
#pragma unroll
    for (int i = 1; i < 8; i++) mx = fmaxf(mx, vals[i]);
    __shared__ float red[8];
#pragma unroll
    for (int o = 16; o; o >>= 1) mx = fmaxf(mx, __shfl_xor_sync(0xffffffffu, mx, o));
    if ((tid & 31) == 0) red[tid >> 5] = mx;
    __syncthreads();
    mx = red[0];
#pragma unroll
    for (int w = 1; w < 8; w++) mx = fmaxf(mx, red[w]);
    __syncthreads();

    float sum = 0.f;
#pragma unroll
    for (int i = 0; i < 8; i++) { vals[i] = __expf(vals[i] - mx); sum += vals[i]; }
#pragma unroll
    for (int o = 16; o; o >>= 1) sum += __shfl_xor_sync(0xffffffffu, sum, o);
    if ((tid & 31) == 0) red[tid >> 5] = sum;
    __syncthreads();
    sum = red[0];
#pragma unroll
    for (int w = 1; w < 8; w++) sum += red[w];
    const float inv = 1.0f / sum;

    alignas(16) __half h[8], l[8];
#pragma unroll
    for (int i = 0; i < 8; i++) split1(vals[i] * inv, h[i], l[i]);
    reinterpret_cast<uint4*>(g_Phi + row * SVAL)[tid] = *reinterpret_cast<uint4*>(h);
    reinterpret_cast<uint4*>(g_Plo + row * SVAL)[tid] = *reinterpret_cast<uint4*>(l);
}

// ---------------------------------------------------------------------------
// ctx[z] = P[z] @ Vt[(m+1)%3, b]^T.  M=2048(s), N=1024(d), K=2048
// ---------------------------------------------------------------------------
__global__ __launch_bounds__(256)
void ctx_kernel()
{
    const int z = blockIdx.z;
    const int m = z >> 2, b = z & 3;
    const int mn = (m + 1) % 3;
    const size_t aoff = (size_t)z * SVAL * SVAL;
    const size_t boff = (size_t)mn * PM + (size_t)b * SVAL;
    const __half* Ah[1] = {g_Phi + aoff};
    const __half* Al[1] = {g_Plo + aoff};
    const __half* Bh[1] = {g_Vthi + boff};
    const __half* Bl[1] = {g_Vtlo + boff};
    __half* Ch = g_Ctxhi + ((size_t)m * BS + (size_t)b * SVAL) * DVAL;
    __half* Cl = g_Ctxlo + ((size_t)m * BS + (size_t)b * SVAL) * DVAL;

    hgemm(Ah, Al, Bh, Bl, 1, 2048, 2048, 8192,
        [=](int r, int c, float v0, float v1) {
            __half h0, l0, h1, l1;
            split1(v0, h0, l0);
            split1(v1, h1, l1);
            size_t o = (size_t)r * DVAL + c;
            *reinterpret_cast<__half2*>(Ch + o) = __halves2half2(h0, h1);
            *reinterpret_cast<__half2*>(Cl + o) = __halves2half2(l0, l1);
        });
}

// ---------------------------------------------------------------------------
// out[m] = [X|Ctx][m] @ WoT[m]^T + bo.  M=8192, N=1024, K=2x1024 (2 segments)
// ---------------------------------------------------------------------------
__global__ __launch_bounds__(256)
void out_kernel(const float* __restrict__ bo, float* __restrict__ out)
{
    const int m = blockIdx.z;
    const size_t xo = (size_t)m * PM;
    const __half* Wh = g_WoThi + (size_t)m * 1024 * 2048;
    const __half* Wl = g_WoTlo + (size_t)m * 1024 * 2048;
    const __half* Ah[2] = {g_Xhi + xo, g_Ctxhi + xo};
    const __half* Al[2] = {g_Xlo + xo, g_Ctxlo + xo};
    const __half* Bh[2] = {Wh, Wh + 1024};
    const __half* Bl[2] = {Wl, Wl + 1024};
    const float* bias = bo + m * 1024;
    float* o_m = out + (size_t)m * PM;
    float* gf  = out + (size_t)3 * PM;

    hgemm(Ah, Al, Bh, Bl, 2, 1024, 1024, 2048,
        [=](int r, int c, float v0, float v1) {
            float2 f;
            f.x = v0 + bias[c];
            f.y = v1 + bias[c + 1];
            const size_t o1 = (size_t)r * DVAL + c;
            const int bb = r >> 11, ss = r & (SVAL - 1);
            const size_t o2 = ((size_t)bb * 3 * SVAL + (size_t)m * SVAL + ss) * DVAL + c;
            *reinterpret_cast<float2*>(o_m + o1) = f;
            *reinterpret_cast<float2*>(gf  + o2) = f;
        });
}

// ---------------------------------------------------------------------------
extern "C" void kernel_launch(void* const* d_in, const int* in_sizes, int n_in,
                              void* d_out, int out_size)
{
    const float* x1 = (const float*)d_in[0];
    const float* x2 = (const float*)d_in[1];
    const float* x3 = (const float*)d_in[2];
    const float* Wq = (const float*)d_in[3];
    const float* bq = (const float*)d_in[4];
    const float* Wk = (const float*)d_in[5];
    const float* bk = (const float*)d_in[6];
    const float* Wv = (const float*)d_in[7];
    const float* bv = (const float*)d_in[8];
    const float* Wo = (const float*)d_in[9];
    const float* bo = (const float*)d_in[10];
    float* out = (float*)d_out;

    // input conversions (destinations resolved in device code)
    conv_x<<<(unsigned)(3 * PM / 4 / 256), 256>>>(x1, x2, x3);
    {
        dim3 blk(32, 8);
        convT_sel<<<dim3(32, 32, 3), blk>>>(Wq, 0, 1024, 1024);
        convT_sel<<<dim3(32, 32, 3), blk>>>(Wk, 1, 1024, 1024);
        convT_sel<<<dim3(32, 32, 3), blk>>>(Wv, 2, 1024, 1024);
        convT_sel<<<dim3(32, 64, 3), blk>>>(Wo, 3, 2048, 1024);
    }

    qk_proj       <<<dim3(8, 64, 6),   256>>>(bq, bk);
    vt_proj       <<<dim3(64, 8, 3),   256>>>(bv);
    scores_kernel <<<dim3(16, 16, 12), 256>>>();
    softmax_kernel<<<3 * BVAL * SVAL,  256>>>();
    ctx_kernel    <<<dim3(8, 16, 12),  256>>>();
    out_kernel    <<<dim3(8, 64, 3),   256>>>(bo, out);
}

// round 11
// speedup vs baseline: 3.4503x; 1.2811x over previous
#include <cuda_runtime.h>
#include <cuda_fp16.h>
#include <mma.h>
#include <cstdint>
#include <math.h>

using namespace nvcuda;

// ---------------------------------------------------------------------------
// Problem constants
// ---------------------------------------------------------------------------
#define BVAL 4
#define SVAL 2048
#define DVAL 1024
constexpr int    BS   = BVAL * SVAL;                     // 8192 rows / modality
constexpr size_t PM   = (size_t)BS * DVAL;               // 8,388,608 / modality
constexpr size_t QKVE = 3 * PM;                          // 25,165,824
constexpr size_t SCE  = (size_t)3 * BVAL * SVAL * SVAL;  // 50,331,648

// ---------------------------------------------------------------------------
// Static device scratch. 2-pass scheme: only A-side operands need lo parts.
// A-side tensors: X, WvT, Q, P, Ctx.  B-side only: Wq/Wk/Wo (hi), K, Vt.
// ---------------------------------------------------------------------------
__device__ __half g_Xhi[QKVE],   g_Xlo[QKVE];
__device__ __half g_Qhi[QKVE],   g_Qlo[QKVE];
__device__ __half g_Khi[QKVE];
__device__ __half g_Vthi[QKVE];                          // V^T: [m][1024][8192]
__device__ __half g_Ctxhi[QKVE], g_Ctxlo[QKVE];
__device__ __half g_Phi[SCE],    g_Plo[SCE];
__device__ float  g_Sc[SCE];
__device__ __half g_WqThi[3*1024*1024];
__device__ __half g_WkThi[3*1024*1024];
__device__ __half g_WvThi[3*1024*1024], g_WvTlo[3*1024*1024];
__device__ __half g_WoThi[3*1024*2048];

// fp16 hi/lo split
__device__ __forceinline__ void split1(float x, __half& h, __half& l) {
    h = __float2half_rn(x);
    l = __float2half_rn(x - __half2float(h));
}

__device__ __forceinline__ uint32_t smem_u32(const void* p) {
    uint32_t a;
    asm("{ .reg .u64 t; cvta.to.shared.u64 t, %1; cvt.u32.u64 %0, t; }"
        : "=r"(a) : "l"(p));
    return a;
}

__device__ __forceinline__ void cpa16(uint32_t dst, const void* src) {
    asm volatile("cp.async.cg.shared.global [%0], [%1], 16;"
                 :: "r"(dst), "l"(src) : "memory");
}

// ---------------------------------------------------------------------------
// Generic 128x128 GEMM on WMMA (m16n16k16, f32 accum), fp16 hi/lo 2-pass:
//   C = sum_seg (Ah+Al)[seg] @ Bh[seg]^T      (B is fp16-quantized; the
//   dropped Ah*Bl correction costs ~1.2e-4 relative noise per GEMM.)
// A[seg]: M x segK row-major (lda); B[seg]: N x segK row-major (ldb).
// 256 threads = 8 warps (4x2); warp tile 32x64. K-chunk 16.
// 4-stage cp.async pipeline; 48 KB static SMEM (4 x 12 KB stages),
// epilogue staging overlays the same SMEM. One __syncthreads per chunk.
// Epi(row, col, v0, v1) consumes 2 adjacent columns.
// ---------------------------------------------------------------------------
template <class Epi>
__device__ void hgemm(const __half* const* Ah, const __half* const* Al,
                      const __half* const* Bh,
                      int nseg, int segK, size_t lda, size_t ldb, Epi epi)
{
    __shared__ __align__(16) unsigned char smraw[49152];   // 4 stages x 12 KB
    float* stage = reinterpret_cast<float*>(smraw);        // epilogue overlay
    const uint32_t sb = smem_u32(smraw);

    const int tid  = threadIdx.x;
    const int lane = tid & 31;
    const int wid  = tid >> 5;
    const int wm   = wid >> 1;        // 0..3 (M groups of 32)
    const int wn   = wid & 1;         // 0..1 (N groups of 64)
    const int rowBase = blockIdx.y * 128;
    const int colBase = blockIdx.x * 128;

    wmma::fragment<wmma::accumulator, 16, 16, 16, float> acc[2][4];
#pragma unroll
    for (int mt = 0; mt < 2; mt++)
#pragma unroll
        for (int nt = 0; nt < 4; nt++) wmma::fill_fragment(acc[mt][nt], 0.0f);

    const int chunksPerSeg = segK >> 4;
    const int nChunks = nseg * chunksPerSeg;

    // loader: thread covers (row lr, 16B-subchunk lc) of each 128x16 tile
    const int lr = tid >> 1;
    const int lc = tid & 1;
    const uint32_t sOffB = (uint32_t)(lr * 16 + lc * 8) * 2u;  // bytes in tile

    auto issue = [&](int cIdx) {
        const int s   = cIdx & 3;
        const int seg = cIdx / chunksPerSeg;
        const int kk  = (cIdx - seg * chunksPerSeg) << 4;
        const size_t ao = (size_t)(rowBase + lr) * lda + kk + lc * 8;
        const size_t bo = (size_t)(colBase + lr) * ldb + kk + lc * 8;
        const uint32_t base = sb + (uint32_t)s * 12288u + sOffB;
        cpa16(base +    0u, Ah[seg] + ao);
        cpa16(base + 4096u, Al[seg] + ao);
        cpa16(base + 8192u, Bh[seg] + bo);
        asm volatile("cp.async.commit_group;" ::: "memory");
    };

    issue(0);
    if (nChunks > 1) issue(1);
    if (nChunks > 2) issue(2);

    for (int c = 0; c < nChunks; c++) {
        const int k = nChunks - c - 1;   // groups allowed to stay in flight
        if (k >= 3)      asm volatile("cp.async.wait_group 2;" ::: "memory");
        else if (k == 2) asm volatile("cp.async.wait_group 2;" ::: "memory");
        else if (k == 1) asm volatile("cp.async.wait_group 1;" ::: "memory");
        else             asm volatile("cp.async.wait_group 0;" ::: "memory");
        __syncthreads();   // stage c visible; compute(c-1) finished by all

        __half* sAh = reinterpret_cast<__half*>(smraw + (c & 3) * 12288);
        __half* sAl = sAh + 2048;
        __half* sBh = sAh + 4096;

        wmma::fragment<wmma::matrix_a, 16, 16, 16, __half, wmma::row_major> fah[2], fal[2];
#pragma unroll
        for (int mt = 0; mt < 2; mt++) {
            const int r = wm * 32 + mt * 16;
            wmma::load_matrix_sync(fah[mt], sAh + r * 16, 16);
            wmma::load_matrix_sync(fal[mt], sAl + r * 16, 16);
        }
#pragma unroll
        for (int nt = 0; nt < 4; nt++) {
            wmma::fragment<wmma::matrix_b, 16, 16, 16, __half, wmma::col_major> fbh;
            const int n = wn * 64 + nt * 16;
            wmma::load_matrix_sync(fbh, sBh + n * 16, 16);
#pragma unroll
            for (int mt = 0; mt < 2; mt++) {
                wmma::mma_sync(acc[mt][nt], fah[mt], fbh, acc[mt][nt]);
                wmma::mma_sync(acc[mt][nt], fal[mt], fbh, acc[mt][nt]);
            }
        }

        // stage (c+3)&3 == (c-1)&3: its last readers (compute c-1) all passed
        // the __syncthreads above, so it is safe to overwrite now.
        if (c + 3 < nChunks) issue(c + 3);
    }

    // epilogue via staging overlay: warp-private 16x64 f32 region
    __syncthreads();   // all compute done before tiles are overwritten
    float* st = stage + wid * 1024;
#pragma unroll
    for (int mt = 0; mt < 2; mt++) {
#pragma unroll
        for (int nt = 0; nt < 4; nt++)
            wmma::store_matrix_sync(st + nt * 16, acc[mt][nt], 64, wmma::mem_row_major);
        __syncwarp();
#pragma unroll
        for (int j = 0; j < 16; j++) {
            float2 v = *reinterpret_cast<float2*>(st + j * 64 + 2 * lane);
            epi(rowBase + wm * 32 + mt * 16 + j, colBase + wn * 64 + 2 * lane, v.x, v.y);
        }
        __syncwarp();
    }
}

// ---------------------------------------------------------------------------
// Conversion: X (fp32) -> Xhi/Xlo  [m][8192][1024]
// ---------------------------------------------------------------------------
__global__ __launch_bounds__(256)
void conv_x(const float* __restrict__ x1, const float* __restrict__ x2,
            const float* __restrict__ x3)
{
    size_t t = (size_t)blockIdx.x * blockDim.x + threadIdx.x;   // float4 index
    const size_t PM4 = PM / 4;
    int m = (int)(t / PM4);
    size_t i = t - (size_t)m * PM4;
    const float* X = (m == 0) ? x1 : (m == 1) ? x2 : x3;
    float4 v = reinterpret_cast<const float4*>(X)[i];
    __half h[4], l[4];
    split1(v.x, h[0], l[0]); split1(v.y, h[1], l[1]);
    split1(v.z, h[2], l[2]); split1(v.w, h[3], l[3]);
    size_t o = (size_t)m * PM + i * 4;
    __half2* ph = reinterpret_cast<__half2*>(g_Xhi + o);
    __half2* pl = reinterpret_cast<__half2*>(g_Xlo + o);
    ph[0] = __halves2half2(h[0], h[1]); ph[1] = __halves2half2(h[2], h[3]);
    pl[0] = __halves2half2(l[0], l[1]); pl[1] = __halves2half2(l[2], l[3]);
}

// ---------------------------------------------------------------------------
// Transpose + split weights: W[m][rows][cols] -> WT[m][cols][rows].
// Destinations resolved IN DEVICE CODE via `sel` (0=Wq,1=Wk,2=Wv,3=Wo) —
// host-passed __device__ symbols resolve to the host shadow (R4-R7 bug).
// Only Wv (sel==2) needs a lo part (it is an A-side operand in vt_proj).
// ---------------------------------------------------------------------------
__global__ void convT_sel(const float* __restrict__ W, int sel, int rows, int cols)
{
    __half* hi;
    __half* lo = nullptr;
    switch (sel) {
        case 0:  hi = g_WqThi; break;
        case 1:  hi = g_WkThi; break;
        case 2:  hi = g_WvThi; lo = g_WvTlo; break;
        default: hi = g_WoThi; break;
    }
    __shared__ float tile[32][33];
    const float* Wm = W + (size_t)blockIdx.z * rows * cols;
    const int c0 = blockIdx.x * 32, r0 = blockIdx.y * 32;
    const int tx = threadIdx.x;
    for (int dy = threadIdx.y; dy < 32; dy += 8)
        tile[dy][tx] = Wm[(size_t)(r0 + dy) * cols + c0 + tx];
    __syncthreads();
    const size_t ob = (size_t)blockIdx.z * rows * cols;
    for (int dy = threadIdx.y; dy < 32; dy += 8) {
        float v = tile[tx][dy];
        __half h, l;
        split1(v, h, l);
        size_t o = ob + (size_t)(c0 + dy) * rows + r0 + tx;
        hi[o] = h;
        if (lo) lo[o] = l;
    }
}

// ---------------------------------------------------------------------------
// Q/K projections. z = m*2 + t (t: 0=Q, 1=K).  M=8192, N=1024, K=1024
// K is only ever a B-side operand -> store hi only for K.
// ---------------------------------------------------------------------------
__global__ __launch_bounds__(256)
void qk_proj(const float* __restrict__ bq, const float* __restrict__ bk)
{
    const int z = blockIdx.z;
    const int m = z >> 1, t = z & 1;
    const __half* Ah[1] = {g_Xhi + (size_t)m * PM};
    const __half* Al[1] = {g_Xlo + (size_t)m * PM};
    const __half* Bh[1] = {(t ? g_WkThi : g_WqThi) + (size_t)m * 1024 * 1024};
    const float* bias = (t ? bk : bq) + m * 1024;
    __half* Ch = (t ? g_Khi : g_Qhi) + (size_t)m * PM;
    __half* Cl = (t ? (__half*)nullptr : g_Qlo + (size_t)m * PM);

    hgemm(Ah, Al, Bh, 1, 1024, 1024, 1024,
        [=](int r, int c, float v0, float v1) {
            __half h0, l0, h1, l1;
            split1(v0 + bias[c],     h0, l0);
            split1(v1 + bias[c + 1], h1, l1);
            size_t o = (size_t)r * 1024 + c;
            *reinterpret_cast<__half2*>(Ch + o) = __halves2half2(h0, h1);
            if (Cl)
                *reinterpret_cast<__half2*>(Cl + o) = __halves2half2(l0, l1);
        });
}

// ---------------------------------------------------------------------------
// V^T projection: Vt[m] = WvT[m] @ X[m]^T + bv.  M=1024(d), N=8192(tok), K=1024
// Vt is only ever a B-side operand -> store hi only.
// ---------------------------------------------------------------------------
__global__ __launch_bounds__(256)
void vt_proj(const float* __restrict__ bv)
{
    const int m = blockIdx.z;
    const __half* Ah[1] = {g_WvThi + (size_t)m * 1024 * 1024};
    const __half* Al[1] = {g_WvTlo + (size_t)m * 1024 * 1024};
    const __half* Bh[1] = {g_Xhi + (size_t)m * PM};
    const float* bias = bv + m * 1024;
    __half* Ch = g_Vthi + (size_t)m * PM;

    hgemm(Ah, Al, Bh, 1, 1024, 1024, 1024,
        [=](int r, int c, float v0, float v1) {
            const float bb = bias[r];
            size_t o = (size_t)r * 8192 + c;
            *reinterpret_cast<__half2*>(Ch + o) =
                __halves2half2(__float2half_rn(v0 + bb), __float2half_rn(v1 + bb));
        });
}

// ---------------------------------------------------------------------------
// scores[z] = Q[z] @ K[z]^T * scale (fp32).  z = m*4+b.  M=N=2048, K=1024
// ---------------------------------------------------------------------------
__global__ __launch_bounds__(256)
void scores_kernel()
{
    const int z = blockIdx.z;
    const size_t off = ((size_t)(z >> 2) * BS + (size_t)(z & 3) * SVAL) * DVAL;
    const __half* Ah[1] = {g_Qhi + off};
    const __half* Al[1] = {g_Qlo + off};
    const __half* Bh[1] = {g_Khi + off};
    float* Sp = g_Sc + (size_t)z * SVAL * SVAL;

    hgemm(Ah, Al, Bh, 1, 1024, 1024, 1024,
        [=](int r, int c, float v0, float v1) {
            float2 f; f.x = v0 * 0.03125f; f.y = v1 * 0.03125f;
            *reinterpret_cast<float2*>(Sp + (size_t)r * SVAL + c) = f;
        });
}

// ---------------------------------------------------------------------------
// softmax rows of 2048: g_Sc (fp32) -> g_Phi/g_Plo (fp16 hi/lo; P is A-side)
// ---------------------------------------------------------------------------
__global__ __launch_bounds__(256)
void softmax_kernel()
{
    const size_t row = blockIdx.x;
    const float* p = g_Sc + row * SVAL;
    const int tid = threadIdx.x;

    float4 v0 = reinterpret_cast<const float4*>(p)[tid * 2];
    float4 v1 = reinterpret_cast<const float4*>(p)[tid * 2 + 1];
    float vals[8] = {v0.x, v0.y, v0.z, v0.w, v1.x, v1.y, v1.z, v1.w};

    float mx = vals[0];
#pragma unroll
    for (int i = 1; i < 8; i++) mx = fmaxf(mx, vals[i]);
    __shared__ float red[8];
#pragma unroll
    for (int o = 16; o; o >>= 1) mx = fmaxf(mx, __shfl_xor_sync(0xffffffffu, mx, o));
    if ((tid & 31) == 0) red[tid >> 5] = mx;
    __syncthreads();
    mx = red[0];
#pragma unroll
    for (int w = 1; w < 8; w++) mx = fmaxf(mx, red[w]);
    __syncthreads();

    float sum = 0.f;
#pragma unroll
    for (int i = 0; i < 8; i++) { vals[i] = __expf(vals[i] - mx); sum += vals[i]; }
#pragma unroll
    for (int o = 16; o; o >>= 1) sum += __shfl_xor_sync(0xffffffffu, sum, o);
    if ((tid & 31) == 0) red[tid >> 5] = sum;
    __syncthreads();
    sum = red[0];
#pragma unroll
    for (int w = 1; w < 8; w++) sum += red[w];
    const float inv = 1.0f / sum;

    alignas(16) __half h[8], l[8];
#pragma unroll
    for (int i = 0; i < 8; i++) split1(vals[i] * inv, h[i], l[i]);
    reinterpret_cast<uint4*>(g_Phi + row * SVAL)[tid] = *reinterpret_cast<uint4*>(h);
    reinterpret_cast<uint4*>(g_Plo + row * SVAL)[tid] = *reinterpret_cast<uint4*>(l);
}

// ---------------------------------------------------------------------------
// ctx[z] = P[z] @ Vt[(m+1)%3, b]^T.  M=2048(s), N=1024(d), K=2048
// Ctx is an A-side operand in out_kernel -> store hi+lo.
// ---------------------------------------------------------------------------
__global__ __launch_bounds__(256)
void ctx_kernel()
{
    const int z = blockIdx.z;
    const int m = z >> 2, b = z & 3;
    const int mn = (m + 1) % 3;
    const size_t aoff = (size_t)z * SVAL * SVAL;
    const size_t boff = (size_t)mn * PM + (size_t)b * SVAL;
    const __half* Ah[1] = {g_Phi + aoff};
    const __half* Al[1] = {g_Plo + aoff};
    const __half* Bh[1] = {g_Vthi + boff};
    __half* Ch = g_Ctxhi + ((size_t)m * BS + (size_t)b * SVAL) * DVAL;
    __half* Cl = g_Ctxlo + ((size_t)m * BS + (size_t)b * SVAL) * DVAL;

    hgemm(Ah, Al, Bh, 1, 2048, 2048, 8192,
        [=](int r, int c, float v0, float v1) {
            __half h0, l0, h1, l1;
            split1(v0, h0, l0);
            split1(v1, h1, l1);
            size_t o = (size_t)r * DVAL + c;
            *reinterpret_cast<__half2*>(Ch + o) = __halves2half2(h0, h1);
            *reinterpret_cast<__half2*>(Cl + o) = __halves2half2(l0, l1);
        });
}

// ---------------------------------------------------------------------------
// out[m] = [X|Ctx][m] @ WoT[m]^T + bo.  M=8192, N=1024, K=2x1024 (2 segments)
// ---------------------------------------------------------------------------
__global__ __launch_bounds__(256)
void out_kernel(const float* __restrict__ bo, float* __restrict__ out)
{
    const int m = blockIdx.z;
    const size_t xo = (size_t)m * PM;
    const __half* Wh = g_WoThi + (size_t)m * 1024 * 2048;
    const __half* Ah[2] = {g_Xhi + xo, g_Ctxhi + xo};
    const __half* Al[2] = {g_Xlo + xo, g_Ctxlo + xo};
    const __half* Bh[2] = {Wh, Wh + 1024};
    const float* bias = bo + m * 1024;
    float* o_m = out + (size_t)m * PM;
    float* gf  = out + (size_t)3 * PM;

    hgemm(Ah, Al, Bh, 2, 1024, 1024, 2048,
        [=](int r, int c, float v0, float v1) {
            float2 f;
            f.x = v0 + bias[c];
            f.y = v1 + bias[c + 1];
            const size_t o1 = (size_t)r * DVAL + c;
            const int bb = r >> 11, ss = r & (SVAL - 1);
            const size_t o2 = ((size_t)bb * 3 * SVAL + (size_t)m * SVAL + ss) * DVAL + c;
            *reinterpret_cast<float2*>(o_m + o1) = f;
            *reinterpret_cast<float2*>(gf  + o2) = f;
        });
}

// ---------------------------------------------------------------------------
extern "C" void kernel_launch(void* const* d_in, const int* in_sizes, int n_in,
                              void* d_out, int out_size)
{
    const float* x1 = (const float*)d_in[0];
    const float* x2 = (const float*)d_in[1];
    const float* x3 = (const float*)d_in[2];
    const float* Wq = (const float*)d_in[3];
    const float* bq = (const float*)d_in[4];
    const float* Wk = (const float*)d_in[5];
    const float* bk = (const float*)d_in[6];
    const float* Wv = (const float*)d_in[7];
    const float* bv = (const float*)d_in[8];
    const float* Wo = (const float*)d_in[9];
    const float* bo = (const float*)d_in[10];
    float* out = (float*)d_out;

    // input conversions (destinations resolved in device code)
    conv_x<<<(unsigned)(3 * PM / 4 / 256), 256>>>(x1, x2, x3);
    {
        dim3 blk(32, 8);
        convT_sel<<<dim3(32, 32, 3), blk>>>(Wq, 0, 1024, 1024);
        convT_sel<<<dim3(32, 32, 3), blk>>>(Wk, 1, 1024, 1024);
        convT_sel<<<dim3(32, 32, 3), blk>>>(Wv, 2, 1024, 1024);
        convT_sel<<<dim3(32, 64, 3), blk>>>(Wo, 3, 2048, 1024);
    }

    qk_proj       <<<dim3(8, 64, 6),   256>>>(bq, bk);
    vt_proj       <<<dim3(64, 8, 3),   256>>>(bv);
    scores_kernel <<<dim3(16, 16, 12), 256>>>();
    softmax_kernel<<<3 * BVAL * SVAL,  256>>>();
    ctx_kernel    <<<dim3(8, 16, 12),  256>>>();
    out_kernel    <<<dim3(8, 64, 3),   256>>>(bo, out);
}

// round 12
// speedup vs baseline: 3.8201x; 1.1072x over previous
#include <cuda_runtime.h>
#include <cuda_fp16.h>
#include <mma.h>
#include <cstdint>
#include <math.h>

using namespace nvcuda;

// ---------------------------------------------------------------------------
// Problem constants
// ---------------------------------------------------------------------------
#define BVAL 4
#define SVAL 2048
#define DVAL 1024
constexpr int    BS   = BVAL * SVAL;                     // 8192 rows / modality
constexpr size_t PM   = (size_t)BS * DVAL;               // 8,388,608 / modality
constexpr size_t QKVE = 3 * PM;                          // 25,165,824
constexpr size_t SCE  = (size_t)3 * BVAL * SVAL * SVAL;  // 50,331,648

// ---------------------------------------------------------------------------
// Static device scratch. Single-pass fp16: hi parts only.
// ---------------------------------------------------------------------------
__device__ __half g_Xhi[QKVE];
__device__ __half g_Qhi[QKVE];
__device__ __half g_Khi[QKVE];
__device__ __half g_Vthi[QKVE];                          // V^T: [m][1024][8192]
__device__ __half g_Ctxhi[QKVE];
__device__ __half g_Phi[SCE];
__device__ float  g_Sc[SCE];
__device__ __half g_WqThi[3*1024*1024];
__device__ __half g_WkThi[3*1024*1024];
__device__ __half g_WvThi[3*1024*1024];
__device__ __half g_WoThi[3*1024*2048];

__device__ __forceinline__ uint32_t smem_u32(const void* p) {
    uint32_t a;
    asm("{ .reg .u64 t; cvta.to.shared.u64 t, %1; cvt.u32.u64 %0, t; }"
        : "=r"(a) : "l"(p));
    return a;
}

__device__ __forceinline__ void cpa16(uint32_t dst, const void* src) {
    asm volatile("cp.async.cg.shared.global [%0], [%1], 16;"
                 :: "r"(dst), "l"(src) : "memory");
}

// ---------------------------------------------------------------------------
// Generic 128x128 GEMM on WMMA (m16n16k16, f32 accum), single-pass fp16:
//   C = sum_seg A[seg] @ B[seg]^T
// A[seg]: M x segK row-major (lda); B[seg]: N x segK row-major (ldb).
// 256 threads = 8 warps (4x2); warp tile 32x64. K-chunk 32.
// 3-stage cp.async pipeline; 48 KB static SMEM (3 x 16 KB stages: A 8K + B 8K),
// epilogue staging overlays the same SMEM. One __syncthreads per 32-K chunk.
// Epi(row, col, v0, v1) consumes 2 adjacent columns. segK multiple of 32.
// ---------------------------------------------------------------------------
template <class Epi>
__device__ void hgemm(const __half* const* Ah, const __half* const* Bh,
                      int nseg, int segK, size_t lda, size_t ldb, Epi epi)
{
    __shared__ __align__(16) unsigned char smraw[49152];   // 3 stages x 16 KB
    float* stage = reinterpret_cast<float*>(smraw);        // epilogue overlay
    const uint32_t sb = smem_u32(smraw);

    const int tid  = threadIdx.x;
    const int lane = tid & 31;
    const int wid  = tid >> 5;
    const int wm   = wid >> 1;        // 0..3 (M groups of 32)
    const int wn   = wid & 1;         // 0..1 (N groups of 64)
    const int rowBase = blockIdx.y * 128;
    const int colBase = blockIdx.x * 128;

    wmma::fragment<wmma::accumulator, 16, 16, 16, float> acc[2][4];
#pragma unroll
    for (int mt = 0; mt < 2; mt++)
#pragma unroll
        for (int nt = 0; nt < 4; nt++) wmma::fill_fragment(acc[mt][nt], 0.0f);

    const int chunksPerSeg = segK >> 5;
    const int nChunks = nseg * chunksPerSeg;

    // loader: each tile is 128 rows x 64 bytes = 512 x 16B chunks;
    // thread covers chunk q = tid and q = tid + 256 (row = q>>2, sub = q&3).
    const int r0 = tid >> 2,  s0 = tid & 3;
    const int r1 = (tid + 256) >> 2;           // sub is the same (tid & 3)
    const uint32_t off0 = (uint32_t)(r0 * 64 + s0 * 16);
    const uint32_t off1 = (uint32_t)(r1 * 64 + s0 * 16);

    auto issue = [&](int cIdx) {
        const int s   = cIdx % 3;
        const int seg = cIdx / chunksPerSeg;
        const int kk  = (cIdx - seg * chunksPerSeg) << 5;
        const uint32_t base = sb + (uint32_t)s * 16384u;
        const __half* Ap = Ah[seg];
        const __half* Bp = Bh[seg];
        cpa16(base + off0,         Ap + (size_t)(rowBase + r0) * lda + kk + s0 * 8);
        cpa16(base + off1,         Ap + (size_t)(rowBase + r1) * lda + kk + s0 * 8);
        cpa16(base + 8192u + off0, Bp + (size_t)(colBase + r0) * ldb + kk + s0 * 8);
        cpa16(base + 8192u + off1, Bp + (size_t)(colBase + r1) * ldb + kk + s0 * 8);
        asm volatile("cp.async.commit_group;" ::: "memory");
    };

    issue(0);
    if (nChunks > 1) issue(1);

    for (int c = 0; c < nChunks; c++) {
        if (c + 1 < nChunks)
            asm volatile("cp.async.wait_group 1;" ::: "memory");
        else
            asm volatile("cp.async.wait_group 0;" ::: "memory");
        __syncthreads();   // stage c visible; compute(c-1) finished by all

        __half* sA = reinterpret_cast<__half*>(smraw + (c % 3) * 16384);
        __half* sB = sA + 4096;   // 8192 bytes into the stage

#pragma unroll
        for (int k = 0; k < 2; k++) {
            wmma::fragment<wmma::matrix_a, 16, 16, 16, __half, wmma::row_major> fah[2];
#pragma unroll
            for (int mt = 0; mt < 2; mt++) {
                const int r = wm * 32 + mt * 16;
                wmma::load_matrix_sync(fah[mt], sA + r * 32 + k * 16, 32);
            }
#pragma unroll
            for (int nt = 0; nt < 4; nt++) {
                wmma::fragment<wmma::matrix_b, 16, 16, 16, __half, wmma::col_major> fbh;
                const int n = wn * 64 + nt * 16;
                wmma::load_matrix_sync(fbh, sB + n * 32 + k * 16, 32);
#pragma unroll
                for (int mt = 0; mt < 2; mt++)
                    wmma::mma_sync(acc[mt][nt], fah[mt], fbh, acc[mt][nt]);
            }
        }

        // stage (c+2)%3 == (c-1)%3: its readers (compute c-1) all passed the
        // __syncthreads above, so it is safe to overwrite now.
        if (c + 2 < nChunks) issue(c + 2);
    }

    // epilogue via staging overlay: warp-private 16x64 f32 region
    __syncthreads();   // all compute done before tiles are overwritten
    float* st = stage + wid * 1024;
#pragma unroll
    for (int mt = 0; mt < 2; mt++) {
#pragma unroll
        for (int nt = 0; nt < 4; nt++)
            wmma::store_matrix_sync(st + nt * 16, acc[mt][nt], 64, wmma::mem_row_major);
        __syncwarp();
#pragma unroll
        for (int j = 0; j < 16; j++) {
            float2 v = *reinterpret_cast<float2*>(st + j * 64 + 2 * lane);
            epi(rowBase + wm * 32 + mt * 16 + j, colBase + wn * 64 + 2 * lane, v.x, v.y);
        }
        __syncwarp();
    }
}

// ---------------------------------------------------------------------------
// Conversion: X (fp32) -> Xhi  [m][8192][1024]
// ---------------------------------------------------------------------------
__global__ __launch_bounds__(256)
void conv_x(const float* __restrict__ x1, const float* __restrict__ x2,
            const float* __restrict__ x3)
{
    size_t t = (size_t)blockIdx.x * blockDim.x + threadIdx.x;   // float4 index
    const size_t PM4 = PM / 4;
    int m = (int)(t / PM4);
    size_t i = t - (size_t)m * PM4;
    const float* X = (m == 0) ? x1 : (m == 1) ? x2 : x3;
    float4 v = reinterpret_cast<const float4*>(X)[i];
    size_t o = (size_t)m * PM + i * 4;
    __half2* ph = reinterpret_cast<__half2*>(g_Xhi + o);
    ph[0] = __halves2half2(__float2half_rn(v.x), __float2half_rn(v.y));
    ph[1] = __halves2half2(__float2half_rn(v.z), __float2half_rn(v.w));
}

// ---------------------------------------------------------------------------
// Transpose + convert weights: W[m][rows][cols] -> WT[m][cols][rows] fp16.
// Destinations resolved IN DEVICE CODE via `sel` (0=Wq,1=Wk,2=Wv,3=Wo) —
// host-passed __device__ symbols resolve to the host shadow (R4-R7 bug).
// ---------------------------------------------------------------------------
__global__ void convT_sel(const float* __restrict__ W, int sel, int rows, int cols)
{
    __half* hi;
    switch (sel) {
        case 0:  hi = g_WqThi; break;
        case 1:  hi = g_WkThi; break;
        case 2:  hi = g_WvThi; break;
        default: hi = g_WoThi; break;
    }
    __shared__ float tile[32][33];
    const float* Wm = W + (size_t)blockIdx.z * rows * cols;
    const int c0 = blockIdx.x * 32, r0 = blockIdx.y * 32;
    const int tx = threadIdx.x;
    for (int dy = threadIdx.y; dy < 32; dy += 8)
        tile[dy][tx] = Wm[(size_t)(r0 + dy) * cols + c0 + tx];
    __syncthreads();
    const size_t ob = (size_t)blockIdx.z * rows * cols;
    for (int dy = threadIdx.y; dy < 32; dy += 8) {
        size_t o = ob + (size_t)(c0 + dy) * rows + r0 + tx;
        hi[o] = __float2half_rn(tile[tx][dy]);
    }
}

// ---------------------------------------------------------------------------
// Q/K projections. z = m*2 + t (t: 0=Q, 1=K).  M=8192, N=1024, K=1024
// ---------------------------------------------------------------------------
__global__ __launch_bounds__(256)
void qk_proj(const float* __restrict__ bq, const float* __restrict__ bk)
{
    const int z = blockIdx.z;
    const int m = z >> 1, t = z & 1;
    const __half* Ah[1] = {g_Xhi + (size_t)m * PM};
    const __half* Bh[1] = {(t ? g_WkThi : g_WqThi) + (size_t)m * 1024 * 1024};
    const float* bias = (t ? bk : bq) + m * 1024;
    __half* Ch = (t ? g_Khi : g_Qhi) + (size_t)m * PM;

    hgemm(Ah, Bh, 1, 1024, 1024, 1024,
        [=](int r, int c, float v0, float v1) {
            size_t o = (size_t)r * 1024 + c;
            *reinterpret_cast<__half2*>(Ch + o) =
                __halves2half2(__float2half_rn(v0 + bias[c]),
                               __float2half_rn(v1 + bias[c + 1]));
        });
}

// ---------------------------------------------------------------------------
// V^T projection: Vt[m] = WvT[m] @ X[m]^T + bv.  M=1024(d), N=8192(tok), K=1024
// ---------------------------------------------------------------------------
__global__ __launch_bounds__(256)
void vt_proj(const float* __restrict__ bv)
{
    const int m = blockIdx.z;
    const __half* Ah[1] = {g_WvThi + (size_t)m * 1024 * 1024};
    const __half* Bh[1] = {g_Xhi + (size_t)m * PM};
    const float* bias = bv + m * 1024;
    __half* Ch = g_Vthi + (size_t)m * PM;

    hgemm(Ah, Bh, 1, 1024, 1024, 1024,
        [=](int r, int c, float v0, float v1) {
            const float bb = bias[r];
            size_t o = (size_t)r * 8192 + c;
            *reinterpret_cast<__half2*>(Ch + o) =
                __halves2half2(__float2half_rn(v0 + bb), __float2half_rn(v1 + bb));
        });
}

// ---------------------------------------------------------------------------
// scores[z] = Q[z] @ K[z]^T * scale (fp32).  z = m*4+b.  M=N=2048, K=1024
// ---------------------------------------------------------------------------
__global__ __launch_bounds__(256)
void scores_kernel()
{
    const int z = blockIdx.z;
    const size_t off = ((size_t)(z >> 2) * BS + (size_t)(z & 3) * SVAL) * DVAL;
    const __half* Ah[1] = {g_Qhi + off};
    const __half* Bh[1] = {g_Khi + off};
    float* Sp = g_Sc + (size_t)z * SVAL * SVAL;

    hgemm(Ah, Bh, 1, 1024, 1024, 1024,
        [=](int r, int c, float v0, float v1) {
            float2 f; f.x = v0 * 0.03125f; f.y = v1 * 0.03125f;
            *reinterpret_cast<float2*>(Sp + (size_t)r * SVAL + c) = f;
        });
}

// ---------------------------------------------------------------------------
// softmax rows of 2048: g_Sc (fp32) -> g_Phi (fp16)
// ---------------------------------------------------------------------------
__global__ __launch_bounds__(256)
void softmax_kernel()
{
    const size_t row = blockIdx.x;
    const float* p = g_Sc + row * SVAL;
    const int tid = threadIdx.x;

    float4 v0 = reinterpret_cast<const float4*>(p)[tid * 2];
    float4 v1 = reinterpret_cast<const float4*>(p)[tid * 2 + 1];
    float vals[8] = {v0.x, v0.y, v0.z, v0.w, v1.x, v1.y, v1.z, v1.w};

    float mx = vals[0];
#pragma unroll
    for (int i = 1; i < 8; i++) mx = fmaxf(mx, vals[i]);
    __shared__ float red[8];
#pragma unroll
    for (int o = 16; o; o >>= 1) mx = fmaxf(mx, __shfl_xor_sync(0xffffffffu, mx, o));
    if ((tid & 31) == 0) red[tid >> 5] = mx;
    __syncthreads();
    mx = red[0];
#pragma unroll
    for (int w = 1; w < 8; w++) mx = fmaxf(mx, red[w]);
    __syncthreads();

    float sum = 0.f;
#pragma unroll
    for (int i = 0; i < 8; i++) { vals[i] = __expf(vals[i] - mx); sum += vals[i]; }
#pragma unroll
    for (int o = 16; o; o >>= 1) sum += __shfl_xor_sync(0xffffffffu, sum, o);
    if ((tid & 31) == 0) red[tid >> 5] = sum;
    __syncthreads();
    sum = red[0];
#pragma unroll
    for (int w = 1; w < 8; w++) sum += red[w];
    const float inv = 1.0f / sum;

    alignas(16) __half h[8];
#pragma unroll
    for (int i = 0; i < 8; i++) h[i] = __float2half_rn(vals[i] * inv);
    reinterpret_cast<uint4*>(g_Phi + row * SVAL)[tid] = *reinterpret_cast<uint4*>(h);
}

// ---------------------------------------------------------------------------
// ctx[z] = P[z] @ Vt[(m+1)%3, b]^T.  M=2048(s), N=1024(d), K=2048
// ---------------------------------------------------------------------------
__global__ __launch_bounds__(256)
void ctx_kernel()
{
    const int z = blockIdx.z;
    const int m = z >> 2, b = z & 3;
    const int mn = (m + 1) % 3;
    const size_t aoff = (size_t)z * SVAL * SVAL;
    const size_t boff = (size_t)mn * PM + (size_t)b * SVAL;
    const __half* Ah[1] = {g_Phi + aoff};
    const __half* Bh[1] = {g_Vthi + boff};
    __half* Ch = g_Ctxhi + ((size_t)m * BS + (size_t)b * SVAL) * DVAL;

    hgemm(Ah, Bh, 1, 2048, 2048, 8192,
        [=](int r, int c, float v0, float v1) {
            size_t o = (size_t)r * DVAL + c;
            *reinterpret_cast<__half2*>(Ch + o) =
                __halves2half2(__float2half_rn(v0), __float2half_rn(v1));
        });
}

// ---------------------------------------------------------------------------
// out[m] = [X|Ctx][m] @ WoT[m]^T + bo.  M=8192, N=1024, K=2x1024 (2 segments)
// ---------------------------------------------------------------------------
__global__ __launch_bounds__(256)
void out_kernel(const float* __restrict__ bo, float* __restrict__ out)
{
    const int m = blockIdx.z;
    const size_t xo = (size_t)m * PM;
    const __half* Wh = g_WoThi + (size_t)m * 1024 * 2048;
    const __half* Ah[2] = {g_Xhi + xo, g_Ctxhi + xo};
    const __half* Bh[2] = {Wh, Wh + 1024};
    const float* bias = bo + m * 1024;
    float* o_m = out + (size_t)m * PM;
    float* gf  = out + (size_t)3 * PM;

    hgemm(Ah, Bh, 2, 1024, 1024, 2048,
        [=](int r, int c, float v0, float v1) {
            float2 f;
            f.x = v0 + bias[c];
            f.y = v1 + bias[c + 1];
            const size_t o1 = (size_t)r * DVAL + c;
            const int bb = r >> 11, ss = r & (SVAL - 1);
            const size_t o2 = ((size_t)bb * 3 * SVAL + (size_t)m * SVAL + ss) * DVAL + c;
            *reinterpret_cast<float2*>(o_m + o1) = f;
            *reinterpret_cast<float2*>(gf  + o2) = f;
        });
}

// ---------------------------------------------------------------------------
extern "C" void kernel_launch(void* const* d_in, const int* in_sizes, int n_in,
                              void* d_out, int out_size)
{
    const float* x1 = (const float*)d_in[0];
    const float* x2 = (const float*)d_in[1];
    const float* x3 = (const float*)d_in[2];
    const float* Wq = (const float*)d_in[3];
    const float* bq = (const float*)d_in[4];
    const float* Wk = (const float*)d_in[5];
    const float* bk = (const float*)d_in[6];
    const float* Wv = (const float*)d_in[7];
    const float* bv = (const float*)d_in[8];
    const float* Wo = (const float*)d_in[9];
    const float* bo = (const float*)d_in[10];
    float* out = (float*)d_out;

    // input conversions (destinations resolved in device code)
    conv_x<<<(unsigned)(3 * PM / 4 / 256), 256>>>(x1, x2, x3);
    {
        dim3 blk(32, 8);
        convT_sel<<<dim3(32, 32, 3), blk>>>(Wq, 0, 1024, 1024);
        convT_sel<<<dim3(32, 32, 3), blk>>>(Wk, 1, 1024, 1024);
        convT_sel<<<dim3(32, 32, 3), blk>>>(Wv, 2, 1024, 1024);
        convT_sel<<<dim3(32, 64, 3), blk>>>(Wo, 3, 2048, 1024);
    }

    qk_proj       <<<dim3(8, 64, 6),   256>>>(bq, bk);
    vt_proj       <<<dim3(64, 8, 3),   256>>>(bv);
    scores_kernel <<<dim3(16, 16, 12), 256>>>();
    softmax_kernel<<<3 * BVAL * SVAL,  256>>>();
    ctx_kernel    <<<dim3(8, 16, 12),  256>>>();
    out_kernel    <<<dim3(8, 64, 3),   256>>>(bo, out);
}

// round 13
// speedup vs baseline: 5.8580x; 1.5335x over previous
#include <cuda_runtime.h>
#include <cuda_fp16.h>
#include <mma.h>
#include <cstdint>
#include <math.h>

using namespace nvcuda;

// ---------------------------------------------------------------------------
// Problem constants
// ---------------------------------------------------------------------------
#define BVAL 4
#define SVAL 2048
#define DVAL 1024
constexpr int    BS   = BVAL * SVAL;                     // 8192 rows / modality
constexpr size_t PM   = (size_t)BS * DVAL;               // 8,388,608 / modality
constexpr size_t QKVE = 3 * PM;                          // 25,165,824
constexpr size_t SCE  = (size_t)3 * BVAL * SVAL * SVAL;  // 50,331,648

// ---------------------------------------------------------------------------
// Static device scratch. Single-pass fp16.
// ---------------------------------------------------------------------------
__device__ __half g_Xhi[QKVE];
__device__ __half g_Qhi[QKVE];
__device__ __half g_Khi[QKVE];
__device__ __half g_Vthi[QKVE];                          // V^T: [m][1024][8192]
__device__ __half g_Ctxhi[QKVE];
__device__ __half g_Phi[SCE];
__device__ float  g_Sc[SCE];
__device__ __half g_WqThi[3*1024*1024];
__device__ __half g_WkThi[3*1024*1024];
__device__ __half g_WvThi[3*1024*1024];
__device__ __half g_WoThi[3*1024*2048];

__device__ __forceinline__ uint32_t smem_u32(const void* p) {
    uint32_t a;
    asm("{ .reg .u64 t; cvta.to.shared.u64 t, %1; cvt.u32.u64 %0, t; }"
        : "=r"(a) : "l"(p));
    return a;
}

__device__ __forceinline__ void cpa16(uint32_t dst, const void* src) {
    asm volatile("cp.async.cg.shared.global [%0], [%1], 16;"
                 :: "r"(dst), "l"(src) : "memory");
}

// ---------------------------------------------------------------------------
// Generic 128x128 GEMM on WMMA (m16n16k16, f32 accum), single-pass fp16:
//   C = sum_seg A[seg] @ B[seg]^T
// A[seg]: M x segK row-major (lda); B[seg]: N x segK row-major (ldb).
// 256 threads = 8 warps (4x2); warp tile 32x64. K-chunk 16.
// Tiles stored with row pitch 24 halves (48 B): 8-row ldmatrix phases hit
// 8 DISTINCT 16B bank slots (48*r mod 128 all distinct) -> conflict-free,
// vs the 64B pitch of R12 which was 4-way conflicted on every fragment load.
// 4-stage cp.async pipeline; 48 KB static SMEM (4 x 12 KB stages: A 6K + B 6K).
// Epilogue staging overlays the same SMEM, padded to ld=68 floats.
// Epi(row, col, v0, v1) consumes 2 adjacent columns. segK multiple of 16.
// ---------------------------------------------------------------------------
constexpr int LDT = 24;   // tile row pitch in halves (48 bytes)

template <class Epi>
__device__ void hgemm(const __half* const* Ah, const __half* const* Bh,
                      int nseg, int segK, size_t lda, size_t ldb, Epi epi)
{
    __shared__ __align__(16) unsigned char smraw[49152];   // 4 stages x 12 KB
    float* stage = reinterpret_cast<float*>(smraw);        // epilogue overlay
    const uint32_t sb = smem_u32(smraw);

    const int tid  = threadIdx.x;
    const int lane = tid & 31;
    const int wid  = tid >> 5;
    const int wm   = wid >> 1;        // 0..3 (M groups of 32)
    const int wn   = wid & 1;         // 0..1 (N groups of 64)
    const int rowBase = blockIdx.y * 128;
    const int colBase = blockIdx.x * 128;

    wmma::fragment<wmma::accumulator, 16, 16, 16, float> acc[2][4];
#pragma unroll
    for (int mt = 0; mt < 2; mt++)
#pragma unroll
        for (int nt = 0; nt < 4; nt++) wmma::fill_fragment(acc[mt][nt], 0.0f);

    const int chunksPerSeg = segK >> 4;
    const int nChunks = nseg * chunksPerSeg;

    // loader: tile = 128 rows x 2 16B-chunks (data 32B/row at pitch 48B);
    // thread covers (row = tid>>1, sub = tid&1): 1 cp.async for A + 1 for B.
    const int lr = tid >> 1;
    const int ls = tid & 1;
    const uint32_t loff = (uint32_t)(lr * 48 + ls * 16);

    auto issue = [&](int cIdx) {
        const int s   = cIdx & 3;
        const int seg = cIdx / chunksPerSeg;
        const int kk  = (cIdx - seg * chunksPerSeg) << 4;
        const uint32_t base = sb + (uint32_t)s * 12288u;
        cpa16(base + loff,         Ah[seg] + (size_t)(rowBase + lr) * lda + kk + ls * 8);
        cpa16(base + 6144u + loff, Bh[seg] + (size_t)(colBase + lr) * ldb + kk + ls * 8);
        asm volatile("cp.async.commit_group;" ::: "memory");
    };

    issue(0);
    if (nChunks > 1) issue(1);
    if (nChunks > 2) issue(2);

    for (int c = 0; c < nChunks; c++) {
        if (c + 2 < nChunks)
            asm volatile("cp.async.wait_group 2;" ::: "memory");
        else if (c + 1 < nChunks)
            asm volatile("cp.async.wait_group 1;" ::: "memory");
        else
            asm volatile("cp.async.wait_group 0;" ::: "memory");
        __syncthreads();   // stage c visible; compute(c-1) finished by all

        __half* sA = reinterpret_cast<__half*>(smraw + (c & 3) * 12288);
        __half* sB = sA + 3072;   // 6144 bytes into the stage

        wmma::fragment<wmma::matrix_a, 16, 16, 16, __half, wmma::row_major> fah[2];
#pragma unroll
        for (int mt = 0; mt < 2; mt++) {
            const int r = wm * 32 + mt * 16;
            wmma::load_matrix_sync(fah[mt], sA + r * LDT, LDT);
        }
#pragma unroll
        for (int nt = 0; nt < 4; nt++) {
            wmma::fragment<wmma::matrix_b, 16, 16, 16, __half, wmma::col_major> fbh;
            const int n = wn * 64 + nt * 16;
            wmma::load_matrix_sync(fbh, sB + n * LDT, LDT);
#pragma unroll
            for (int mt = 0; mt < 2; mt++)
                wmma::mma_sync(acc[mt][nt], fah[mt], fbh, acc[mt][nt]);
        }

        // stage (c+3)&3 == (c-1)&3: its readers (compute c-1) all passed the
        // __syncthreads above, so it is safe to overwrite now.
        if (c + 3 < nChunks) issue(c + 3);
    }

    // epilogue via staging overlay: warp-private 16x64 f32 region, ld=68 pad
    __syncthreads();   // all compute done before tiles are overwritten
    float* st = stage + wid * 1088;   // 16*68 floats per warp
#pragma unroll
    for (int mt = 0; mt < 2; mt++) {
#pragma unroll
        for (int nt = 0; nt < 4; nt++)
            wmma::store_matrix_sync(st + nt * 16, acc[mt][nt], 68, wmma::mem_row_major);
        __syncwarp();
#pragma unroll
        for (int j = 0; j < 16; j++) {
            float2 v = *reinterpret_cast<float2*>(st + j * 68 + 2 * lane);
            epi(rowBase + wm * 32 + mt * 16 + j, colBase + wn * 64 + 2 * lane, v.x, v.y);
        }
        __syncwarp();
    }
}

// ---------------------------------------------------------------------------
// Conversion: X (fp32) -> Xhi  [m][8192][1024]
// ---------------------------------------------------------------------------
__global__ __launch_bounds__(256)
void conv_x(const float* __restrict__ x1, const float* __restrict__ x2,
            const float* __restrict__ x3)
{
    size_t t = (size_t)blockIdx.x * blockDim.x + threadIdx.x;   // float4 index
    const size_t PM4 = PM / 4;
    int m = (int)(t / PM4);
    size_t i = t - (size_t)m * PM4;
    const float* X = (m == 0) ? x1 : (m == 1) ? x2 : x3;
    float4 v = reinterpret_cast<const float4*>(X)[i];
    size_t o = (size_t)m * PM + i * 4;
    __half2* ph = reinterpret_cast<__half2*>(g_Xhi + o);
    ph[0] = __halves2half2(__float2half_rn(v.x), __float2half_rn(v.y));
    ph[1] = __halves2half2(__float2half_rn(v.z), __float2half_rn(v.w));
}

// ---------------------------------------------------------------------------
// Transpose + convert weights: W[m][rows][cols] -> WT[m][cols][rows] fp16.
// Destinations resolved IN DEVICE CODE via `sel` (0=Wq,1=Wk,2=Wv,3=Wo) —
// host-passed __device__ symbols resolve to the host shadow (R4-R7 bug).
// ---------------------------------------------------------------------------
__global__ void convT_sel(const float* __restrict__ W, int sel, int rows, int cols)
{
    __half* hi;
    switch (sel) {
        case 0:  hi = g_WqThi; break;
        case 1:  hi = g_WkThi; break;
        case 2:  hi = g_WvThi; break;
        default: hi = g_WoThi; break;
    }
    __shared__ float tile[32][33];
    const float* Wm = W + (size_t)blockIdx.z * rows * cols;
    const int c0 = blockIdx.x * 32, r0 = blockIdx.y * 32;
    const int tx = threadIdx.x;
    for (int dy = threadIdx.y; dy < 32; dy += 8)
        tile[dy][tx] = Wm[(size_t)(r0 + dy) * cols + c0 + tx];
    __syncthreads();
    const size_t ob = (size_t)blockIdx.z * rows * cols;
    for (int dy = threadIdx.y; dy < 32; dy += 8) {
        size_t o = ob + (size_t)(c0 + dy) * rows + r0 + tx;
        hi[o] = __float2half_rn(tile[tx][dy]);
    }
}

// ---------------------------------------------------------------------------
// Q/K projections. z = m*2 + t (t: 0=Q, 1=K).  M=8192, N=1024, K=1024
// ---------------------------------------------------------------------------
__global__ __launch_bounds__(256)
void qk_proj(const float* __restrict__ bq, const float* __restrict__ bk)
{
    const int z = blockIdx.z;
    const int m = z >> 1, t = z & 1;
    const __half* Ah[1] = {g_Xhi + (size_t)m * PM};
    const __half* Bh[1] = {(t ? g_WkThi : g_WqThi) + (size_t)m * 1024 * 1024};
    const float* bias = (t ? bk : bq) + m * 1024;
    __half* Ch = (t ? g_Khi : g_Qhi) + (size_t)m * PM;

    hgemm(Ah, Bh, 1, 1024, 1024, 1024,
        [=](int r, int c, float v0, float v1) {
            size_t o = (size_t)r * 1024 + c;
            *reinterpret_cast<__half2*>(Ch + o) =
                __halves2half2(__float2half_rn(v0 + bias[c]),
                               __float2half_rn(v1 + bias[c + 1]));
        });
}

// ---------------------------------------------------------------------------
// V^T projection: Vt[m] = WvT[m] @ X[m]^T + bv.  M=1024(d), N=8192(tok), K=1024
// ---------------------------------------------------------------------------
__global__ __launch_bounds__(256)
void vt_proj(const float* __restrict__ bv)
{
    const int m = blockIdx.z;
    const __half* Ah[1] = {g_WvThi + (size_t)m * 1024 * 1024};
    const __half* Bh[1] = {g_Xhi + (size_t)m * PM};
    const float* bias = bv + m * 1024;
    __half* Ch = g_Vthi + (size_t)m * PM;

    hgemm(Ah, Bh, 1, 1024, 1024, 1024,
        [=](int r, int c, float v0, float v1) {
            const float bb = bias[r];
            size_t o = (size_t)r * 8192 + c;
            *reinterpret_cast<__half2*>(Ch + o) =
                __halves2half2(__float2half_rn(v0 + bb), __float2half_rn(v1 + bb));
        });
}

// ---------------------------------------------------------------------------
// scores[z] = Q[z] @ K[z]^T * scale (fp32).  z = m*4+b.  M=N=2048, K=1024
// ---------------------------------------------------------------------------
__global__ __launch_bounds__(256)
void scores_kernel()
{
    const int z = blockIdx.z;
    const size_t off = ((size_t)(z >> 2) * BS + (size_t)(z & 3) * SVAL) * DVAL;
    const __half* Ah[1] = {g_Qhi + off};
    const __half* Bh[1] = {g_Khi + off};
    float* Sp = g_Sc + (size_t)z * SVAL * SVAL;

    hgemm(Ah, Bh, 1, 1024, 1024, 1024,
        [=](int r, int c, float v0, float v1) {
            float2 f; f.x = v0 * 0.03125f; f.y = v1 * 0.03125f;
            *reinterpret_cast<float2*>(Sp + (size_t)r * SVAL + c) = f;
        });
}

// ---------------------------------------------------------------------------
// softmax rows of 2048: g_Sc (fp32) -> g_Phi (fp16)
// ---------------------------------------------------------------------------
__global__ __launch_bounds__(256)
void softmax_kernel()
{
    const size_t row = blockIdx.x;
    const float* p = g_Sc + row * SVAL;
    const int tid = threadIdx.x;

    float4 v0 = reinterpret_cast<const float4*>(p)[tid * 2];
    float4 v1 = reinterpret_cast<const float4*>(p)[tid * 2 + 1];
    float vals[8] = {v0.x, v0.y, v0.z, v0.w, v1.x, v1.y, v1.z, v1.w};

    float mx = vals[0];
#pragma unroll
    for (int i = 1; i < 8; i++) mx = fmaxf(mx, vals[i]);
    __shared__ float red[8];
#pragma unroll
    for (int o = 16; o; o >>= 1) mx = fmaxf(mx, __shfl_xor_sync(0xffffffffu, mx, o));
    if ((tid & 31) == 0) red[tid >> 5] = mx;
    __syncthreads();
    mx = red[0];
#pragma unroll
    for (int w = 1; w < 8; w++) mx = fmaxf(mx, red[w]);
    __syncthreads();

    float sum = 0.f;
#pragma unroll
    for (int i = 0; i < 8; i++) { vals[i] = __expf(vals[i] - mx); sum += vals[i]; }
#pragma unroll
    for (int o = 16; o; o >>= 1) sum += __shfl_xor_sync(0xffffffffu, sum, o);
    if ((tid & 31) == 0) red[tid >> 5] = sum;
    __syncthreads();
    sum = red[0];
#pragma unroll
    for (int w = 1; w < 8; w++) sum += red[w];
    const float inv = 1.0f / sum;

    alignas(16) __half h[8];
#pragma unroll
    for (int i = 0; i < 8; i++) h[i] = __float2half_rn(vals[i] * inv);
    reinterpret_cast<uint4*>(g_Phi + row * SVAL)[tid] = *reinterpret_cast<uint4*>(h);
}

// ---------------------------------------------------------------------------
// ctx[z] = P[z] @ Vt[(m+1)%3, b]^T.  M=2048(s), N=1024(d), K=2048
// ---------------------------------------------------------------------------
__global__ __launch_bounds__(256)
void ctx_kernel()
{
    const int z = blockIdx.z;
    const int m = z >> 2, b = z & 3;
    const int mn = (m + 1) % 3;
    const size_t aoff = (size_t)z * SVAL * SVAL;
    const size_t boff = (size_t)mn * PM + (size_t)b * SVAL;
    const __half* Ah[1] = {g_Phi + aoff};
    const __half* Bh[1] = {g_Vthi + boff};
    __half* Ch = g_Ctxhi + ((size_t)m * BS + (size_t)b * SVAL) * DVAL;

    hgemm(Ah, Bh, 1, 2048, 2048, 8192,
        [=](int r, int c, float v0, float v1) {
            size_t o = (size_t)r * DVAL + c;
            *reinterpret_cast<__half2*>(Ch + o) =
                __halves2half2(__float2half_rn(v0), __float2half_rn(v1));
        });
}

// ---------------------------------------------------------------------------
// out[m] = [X|Ctx][m] @ WoT[m]^T + bo.  M=8192, N=1024, K=2x1024 (2 segments)
// ---------------------------------------------------------------------------
__global__ __launch_bounds__(256)
void out_kernel(const float* __restrict__ bo, float* __restrict__ out)
{
    const int m = blockIdx.z;
    const size_t xo = (size_t)m * PM;
    const __half* Wh = g_WoThi + (size_t)m * 1024 * 2048;
    const __half* Ah[2] = {g_Xhi + xo, g_Ctxhi + xo};
    const __half* Bh[2] = {Wh, Wh + 1024};
    const float* bias = bo + m * 1024;
    float* o_m = out + (size_t)m * PM;
    float* gf  = out + (size_t)3 * PM;

    hgemm(Ah, Bh, 2, 1024, 1024, 2048,
        [=](int r, int c, float v0, float v1) {
            float2 f;
            f.x = v0 + bias[c];
            f.y = v1 + bias[c + 1];
            const size_t o1 = (size_t)r * DVAL + c;
            const int bb = r >> 11, ss = r & (SVAL - 1);
            const size_t o2 = ((size_t)bb * 3 * SVAL + (size_t)m * SVAL + ss) * DVAL + c;
            *reinterpret_cast<float2*>(o_m + o1) = f;
            *reinterpret_cast<float2*>(gf  + o2) = f;
        });
}

// ---------------------------------------------------------------------------
extern "C" void kernel_launch(void* const* d_in, const int* in_sizes, int n_in,
                              void* d_out, int out_size)
{
    const float* x1 = (const float*)d_in[0];
    const float* x2 = (const float*)d_in[1];
    const float* x3 = (const float*)d_in[2];
    const float* Wq = (const float*)d_in[3];
    const float* bq = (const float*)d_in[4];
    const float* Wk = (const float*)d_in[5];
    const float* bk = (const float*)d_in[6];
    const float* Wv = (const float*)d_in[7];
    const float* bv = (const float*)d_in[8];
    const float* Wo = (const float*)d_in[9];
    const float* bo = (const float*)d_in[10];
    float* out = (float*)d_out;

    // input conversions (destinations resolved in device code)
    conv_x<<<(unsigned)(3 * PM / 4 / 256), 256>>>(x1, x2, x3);
    {
        dim3 blk(32, 8);
        convT_sel<<<dim3(32, 32, 3), blk>>>(Wq, 0, 1024, 1024);
        convT_sel<<<dim3(32, 32, 3), blk>>>(Wk, 1, 1024, 1024);
        convT_sel<<<dim3(32, 32, 3), blk>>>(Wv, 2, 1024, 1024);
        convT_sel<<<dim3(32, 64, 3), blk>>>(Wo, 3, 2048, 1024);
    }

    qk_proj       <<<dim3(8, 64, 6),   256>>>(bq, bk);
    vt_proj       <<<dim3(64, 8, 3),   256>>>(bv);
    scores_kernel <<<dim3(16, 16, 12), 256>>>();
    softmax_kernel<<<3 * BVAL * SVAL,  256>>>();
    ctx_kernel    <<<dim3(8, 16, 12),  256>>>();
    out_kernel    <<<dim3(8, 64, 3),   256>>>(bo, out);
}